// round 1
// baseline (speedup 1.0000x reference)
#include <cuda_runtime.h>

#define BB 2
#define SS_ 2048
#define DD 1024
#define HH 16
#define HD 64
#define M_TOT (BB * SS_)        // 4096
#define BH (BB * HH)            // 32
#define SSQ ((size_t)SS_ * SS_) // 4194304 per (b,h)

// -------- scratch (device globals; no runtime allocation) --------
__device__ float g_q[(size_t)BB * HH * SS_ * HD];   // 16 MB
__device__ float g_k[(size_t)BB * HH * SS_ * HD];   // 16 MB
__device__ float g_v[(size_t)BB * HH * SS_ * HD];   // 16 MB
__device__ float g_p[(size_t)BB * HH * SS_ * SS_];  // 536 MB: scores -> probs
__device__ float g_ctx[(size_t)BB * HH * SS_ * HD]; // 16 MB

// ============================================================================
// Projection GEMM: Y = X[4096,1024] @ W[1024,1024] + b, stored permuted to
// [B,H,S,Hd].  which: 0->g_q, 1->g_k, 2->g_v
// 64x64 tile, BK=16, 256 threads, 4x4 microtile.
// ============================================================================
__global__ __launch_bounds__(256) void proj_kernel(
    const float* __restrict__ X, const float* __restrict__ W,
    const float* __restrict__ bias, int which)
{
    __shared__ float As[16][68];
    __shared__ float Bs[16][68];
    float* __restrict__ Out = (which == 0) ? g_q : (which == 1) ? g_k : g_v;

    const int m0 = blockIdx.x * 64;
    const int n0 = blockIdx.y * 64;
    const int tid = threadIdx.x;
    const int tx = tid & 15, ty = tid >> 4;

    float acc[4][4] = {};

    for (int k0 = 0; k0 < DD; k0 += 16) {
        {   // A: 64 rows x 16 cols, 1 float4/thread, store transposed
            int m = tid >> 2, kq = tid & 3;
            float4 a = *(const float4*)(X + (size_t)(m0 + m) * DD + k0 + kq * 4);
            As[kq * 4 + 0][m] = a.x; As[kq * 4 + 1][m] = a.y;
            As[kq * 4 + 2][m] = a.z; As[kq * 4 + 3][m] = a.w;
        }
        {   // B: 16 rows x 64 cols, 1 float4/thread
            int kk = tid >> 4, nq = tid & 15;
            *(float4*)&Bs[kk][nq * 4] =
                *(const float4*)(W + (size_t)(k0 + kk) * DD + n0 + nq * 4);
        }
        __syncthreads();
#pragma unroll
        for (int k = 0; k < 16; k++) {
            float4 ra = *(const float4*)&As[k][ty * 4];
            float4 rb = *(const float4*)&Bs[k][tx * 4];
            float a_[4] = {ra.x, ra.y, ra.z, ra.w};
            float b_[4] = {rb.x, rb.y, rb.z, rb.w};
#pragma unroll
            for (int i = 0; i < 4; i++)
#pragma unroll
                for (int j = 0; j < 4; j++)
                    acc[i][j] = fmaf(a_[i], b_[j], acc[i][j]);
        }
        __syncthreads();
    }

#pragma unroll
    for (int i = 0; i < 4; i++) {
        int m = m0 + ty * 4 + i;
        int b = m >> 11, s = m & (SS_ - 1);
#pragma unroll
        for (int j = 0; j < 4; j++) {
            int n = n0 + tx * 4 + j;
            int h = n >> 6, dh = n & 63;
            Out[(((size_t)(b * HH + h)) * SS_ + s) * HD + dh] = acc[i][j] + bias[n];
        }
    }
}

// ============================================================================
// Scores: per (b,h):  Sb[q,k] = (Q[q,:] . K[k,:]) / 8
// GEMM M=N=2048, K=64 (single full-K tile). 64x64 tile, 256 thr, 4x4 micro.
// grid (32, 32, 32)
// ============================================================================
__global__ __launch_bounds__(256) void scores_kernel()
{
    __shared__ float Qs[64][68];
    __shared__ float Ks[64][68];

    const int bh = blockIdx.z;
    const int m0 = blockIdx.x * 64;
    const int n0 = blockIdx.y * 64;
    const float* __restrict__ Q = g_q + (size_t)bh * SS_ * HD;
    const float* __restrict__ K = g_k + (size_t)bh * SS_ * HD;

    const int tid = threadIdx.x;
    const int tx = tid & 15, ty = tid >> 4;

#pragma unroll
    for (int r = 0; r < 4; r++) {
        int id = tid + r * 256;          // 0..1023
        int m = id >> 4, kq = id & 15;   // 64 rows x 16 float4
        float4 q4 = *(const float4*)(Q + (size_t)(m0 + m) * HD + kq * 4);
        Qs[kq * 4 + 0][m] = q4.x; Qs[kq * 4 + 1][m] = q4.y;
        Qs[kq * 4 + 2][m] = q4.z; Qs[kq * 4 + 3][m] = q4.w;
        float4 k4 = *(const float4*)(K + (size_t)(n0 + m) * HD + kq * 4);
        Ks[kq * 4 + 0][m] = k4.x; Ks[kq * 4 + 1][m] = k4.y;
        Ks[kq * 4 + 2][m] = k4.z; Ks[kq * 4 + 3][m] = k4.w;
    }
    __syncthreads();

    float acc[4][4] = {};
#pragma unroll
    for (int k = 0; k < 64; k++) {
        float4 ra = *(const float4*)&Qs[k][ty * 4];
        float4 rb = *(const float4*)&Ks[k][tx * 4];
        float a_[4] = {ra.x, ra.y, ra.z, ra.w};
        float b_[4] = {rb.x, rb.y, rb.z, rb.w};
#pragma unroll
        for (int i = 0; i < 4; i++)
#pragma unroll
            for (int j = 0; j < 4; j++)
                acc[i][j] = fmaf(a_[i], b_[j], acc[i][j]);
    }

    float* __restrict__ Sb = g_p + (size_t)bh * SSQ;
    const float scale = 0.125f;  // 1/sqrt(64)
#pragma unroll
    for (int i = 0; i < 4; i++) {
        size_t row = (size_t)(m0 + ty * 4 + i) * SS_;
#pragma unroll
        for (int j = 0; j < 4; j++)
            Sb[row + n0 + tx * 4 + j] = acc[i][j] * scale;
    }
}

// ============================================================================
// Row softmax in place over g_p. One block (256 threads) per row of 2048.
// grid = B*H*S = 65536
// ============================================================================
__global__ __launch_bounds__(256) void softmax_kernel()
{
    float* __restrict__ p = g_p + (size_t)blockIdx.x * SS_;
    const int tid = threadIdx.x;
    __shared__ float sm[8];

    float v[8];
    float mx = -3.4e38f;
#pragma unroll
    for (int i = 0; i < 8; i++) { v[i] = p[tid + i * 256]; mx = fmaxf(mx, v[i]); }
#pragma unroll
    for (int o = 16; o; o >>= 1) mx = fmaxf(mx, __shfl_xor_sync(~0u, mx, o));
    if ((tid & 31) == 0) sm[tid >> 5] = mx;
    __syncthreads();
    mx = sm[0];
#pragma unroll
    for (int i = 1; i < 8; i++) mx = fmaxf(mx, sm[i]);
    __syncthreads();

    float sum = 0.f;
#pragma unroll
    for (int i = 0; i < 8; i++) { v[i] = __expf(v[i] - mx); sum += v[i]; }
#pragma unroll
    for (int o = 16; o; o >>= 1) sum += __shfl_xor_sync(~0u, sum, o);
    if ((tid & 31) == 0) sm[tid >> 5] = sum;
    __syncthreads();
    float total = 0.f;
#pragma unroll
    for (int i = 0; i < 8; i++) total += sm[i];

    float inv = 1.0f / total;
#pragma unroll
    for (int i = 0; i < 8; i++) p[tid + i * 256] = v[i] * inv;
}

// ============================================================================
// attn_mean[b,q,k] = mean over heads of P. float4 per thread.
// ============================================================================
__global__ __launch_bounds__(256) void mean_kernel(float* __restrict__ attn_mean)
{
    size_t i4 = (size_t)blockIdx.x * 256 + threadIdx.x;   // over B*S*S/4
    size_t per_b = SSQ / 4;
    size_t b = i4 / per_b;
    size_t r4 = i4 - b * per_b;
    const float4* base = (const float4*)g_p + b * (size_t)HH * per_b + r4;
    float4 acc = {0.f, 0.f, 0.f, 0.f};
#pragma unroll
    for (int h = 0; h < HH; h++) {
        float4 t = base[(size_t)h * per_b];
        acc.x += t.x; acc.y += t.y; acc.z += t.z; acc.w += t.w;
    }
    const float inv = 1.0f / 16.0f;
    float4 o = {acc.x * inv, acc.y * inv, acc.z * inv, acc.w * inv};
    ((float4*)attn_mean)[i4] = o;
}

// ============================================================================
// ctx = P @ V per (b,h): M=2048, N=64, K=2048. 64x64 tile, BK=32.
// grid (32, 32[bh])
// ============================================================================
__global__ __launch_bounds__(256) void ctx_kernel()
{
    __shared__ float As[32][68];
    __shared__ float Bs[32][68];

    const int bh = blockIdx.y;
    const int m0 = blockIdx.x * 64;
    const float* __restrict__ P = g_p + (size_t)bh * SSQ;
    const float* __restrict__ V = g_v + (size_t)bh * SS_ * HD;

    const int tid = threadIdx.x;
    const int tx = tid & 15, ty = tid >> 4;
    float acc[4][4] = {};

    for (int k0 = 0; k0 < SS_; k0 += 32) {
#pragma unroll
        for (int r = 0; r < 2; r++) {
            int id = tid + r * 256;              // 0..511
            int m = id >> 3, kq = id & 7;        // A: 64 rows x 8 float4
            float4 a = *(const float4*)(P + (size_t)(m0 + m) * SS_ + k0 + kq * 4);
            As[kq * 4 + 0][m] = a.x; As[kq * 4 + 1][m] = a.y;
            As[kq * 4 + 2][m] = a.z; As[kq * 4 + 3][m] = a.w;
            int kk = id >> 4, nq = id & 15;      // B: 32 rows x 16 float4
            *(float4*)&Bs[kk][nq * 4] =
                *(const float4*)(V + (size_t)(k0 + kk) * HD + nq * 4);
        }
        __syncthreads();
#pragma unroll
        for (int k = 0; k < 32; k++) {
            float4 ra = *(const float4*)&As[k][ty * 4];
            float4 rb = *(const float4*)&Bs[k][tx * 4];
            float a_[4] = {ra.x, ra.y, ra.z, ra.w};
            float b_[4] = {rb.x, rb.y, rb.z, rb.w};
#pragma unroll
            for (int i = 0; i < 4; i++)
#pragma unroll
                for (int j = 0; j < 4; j++)
                    acc[i][j] = fmaf(a_[i], b_[j], acc[i][j]);
        }
        __syncthreads();
    }

    float* __restrict__ C = g_ctx + (size_t)bh * SS_ * HD;
#pragma unroll
    for (int i = 0; i < 4; i++) {
        size_t row = (size_t)(m0 + ty * 4 + i) * HD;
#pragma unroll
        for (int j = 0; j < 4; j++)
            C[row + tx * 4 + j] = acc[i][j];
    }
}

// ============================================================================
// out = Ctx2[4096,1024] @ Wo + bo, where Ctx2[m, h*64+dh] = g_ctx[b,h,s,dh].
// Same shape as proj_kernel; A loads gather per-head base (16-wide k chunks
// never cross a head boundary).
// ============================================================================
__global__ __launch_bounds__(256) void out_kernel(
    const float* __restrict__ Wo, const float* __restrict__ bo,
    float* __restrict__ out)
{
    __shared__ float As[16][68];
    __shared__ float Bs[16][68];

    const int m0 = blockIdx.x * 64;
    const int n0 = blockIdx.y * 64;
    const int tid = threadIdx.x;
    const int tx = tid & 15, ty = tid >> 4;

    float acc[4][4] = {};

    for (int k0 = 0; k0 < DD; k0 += 16) {
        {
            int m = tid >> 2, kq = tid & 3;
            int mm = m0 + m;
            int b = mm >> 11, s = mm & (SS_ - 1);
            int h = k0 >> 6, dh = k0 & 63;
            const float* arow =
                g_ctx + (((size_t)(b * HH + h)) * SS_ + s) * HD + dh;
            float4 a = *(const float4*)(arow + kq * 4);
            As[kq * 4 + 0][m] = a.x; As[kq * 4 + 1][m] = a.y;
            As[kq * 4 + 2][m] = a.z; As[kq * 4 + 3][m] = a.w;
        }
        {
            int kk = tid >> 4, nq = tid & 15;
            *(float4*)&Bs[kk][nq * 4] =
                *(const float4*)(Wo + (size_t)(k0 + kk) * DD + n0 + nq * 4);
        }
        __syncthreads();
#pragma unroll
        for (int k = 0; k < 16; k++) {
            float4 ra = *(const float4*)&As[k][ty * 4];
            float4 rb = *(const float4*)&Bs[k][tx * 4];
            float a_[4] = {ra.x, ra.y, ra.z, ra.w};
            float b_[4] = {rb.x, rb.y, rb.z, rb.w};
#pragma unroll
            for (int i = 0; i < 4; i++)
#pragma unroll
                for (int j = 0; j < 4; j++)
                    acc[i][j] = fmaf(a_[i], b_[j], acc[i][j]);
        }
        __syncthreads();
    }

#pragma unroll
    for (int i = 0; i < 4; i++) {
        size_t m = (size_t)(m0 + ty * 4 + i);
#pragma unroll
        for (int j = 0; j < 4; j++) {
            int n = n0 + tx * 4 + j;
            out[m * DD + n] = acc[i][j] + bo[n];
        }
    }
}

// ============================================================================
extern "C" void kernel_launch(void* const* d_in, const int* in_sizes, int n_in,
                              void* d_out, int out_size)
{
    const float* x  = (const float*)d_in[0];
    const float* Wq = (const float*)d_in[1];
    const float* bq = (const float*)d_in[2];
    const float* Wk = (const float*)d_in[3];
    const float* bk = (const float*)d_in[4];
    const float* Wv = (const float*)d_in[5];
    const float* bv = (const float*)d_in[6];
    const float* Wo = (const float*)d_in[7];
    const float* bo = (const float*)d_in[8];

    float* out = (float*)d_out;                        // [B,S,D]
    float* attn_mean = out + (size_t)BB * SS_ * DD;    // [B,S,S]

    dim3 gp(M_TOT / 64, DD / 64);        // (64,16)
    proj_kernel<<<gp, 256>>>(x, Wq, bq, 0);
    proj_kernel<<<gp, 256>>>(x, Wk, bk, 1);
    proj_kernel<<<gp, 256>>>(x, Wv, bv, 2);

    dim3 gs(SS_ / 64, SS_ / 64, BH);     // (32,32,32)
    scores_kernel<<<gs, 256>>>();

    softmax_kernel<<<BH * SS_, 256>>>(); // 65536 rows

    mean_kernel<<<(unsigned)((size_t)BB * SSQ / 4 / 256), 256>>>(attn_mean);

    dim3 gc(SS_ / 64, BH);               // (32,32)
    ctx_kernel<<<gc, 256>>>();

    out_kernel<<<gp, 256>>>(Wo, bo, out);
}

// round 5
// speedup vs baseline: 1.1825x; 1.1825x over previous
#include <cuda_runtime.h>
#include <cuda_bf16.h>
#include <cstdint>

#define BB 2
#define SS_ 2048
#define DD 1024
#define HH 16
#define HD 64
#define M_TOT (BB * SS_)        // 4096
#define BH (BB * HH)            // 32
#define SSQ ((size_t)SS_ * SS_) // 4194304 per (b,h)

// -------- scratch (device globals; no runtime allocation) --------
__device__ float g_q[(size_t)BB * HH * SS_ * HD];   // 16 MB
__device__ float g_k[(size_t)BB * HH * SS_ * HD];   // 16 MB
__device__ float g_v[(size_t)BB * HH * SS_ * HD];   // 16 MB
__device__ float g_p[(size_t)BB * HH * SS_ * SS_];  // 536 MB: scores -> probs
__device__ float g_ctx[(size_t)BB * HH * SS_ * HD]; // 16 MB
// bf16 hi/lo split of q, k for the tensor-core scores path (+32 MB)
__device__ __align__(256) __nv_bfloat16 g_qh[(size_t)BH * SS_ * HD];
__device__ __align__(256) __nv_bfloat16 g_ql[(size_t)BH * SS_ * HD];
__device__ __align__(256) __nv_bfloat16 g_kh[(size_t)BH * SS_ * HD];
__device__ __align__(256) __nv_bfloat16 g_kl[(size_t)BH * SS_ * HD];

// ============================================================================
// Projection GEMM (UNCHANGED from R1, proven)
// ============================================================================
__global__ __launch_bounds__(256) void proj_kernel(
    const float* __restrict__ X, const float* __restrict__ W,
    const float* __restrict__ bias, int which)
{
    __shared__ __align__(16) float As[16][68];
    __shared__ __align__(16) float Bs[16][68];
    float* __restrict__ Out = (which == 0) ? g_q : (which == 1) ? g_k : g_v;

    const int m0 = blockIdx.x * 64;
    const int n0 = blockIdx.y * 64;
    const int tid = threadIdx.x;
    const int tx = tid & 15, ty = tid >> 4;

    float acc[4][4] = {};

    for (int k0 = 0; k0 < DD; k0 += 16) {
        {
            int m = tid >> 2, kq = tid & 3;
            float4 a = *(const float4*)(X + (size_t)(m0 + m) * DD + k0 + kq * 4);
            As[kq * 4 + 0][m] = a.x; As[kq * 4 + 1][m] = a.y;
            As[kq * 4 + 2][m] = a.z; As[kq * 4 + 3][m] = a.w;
        }
        {
            int kk = tid >> 4, nq = tid & 15;
            *(float4*)&Bs[kk][nq * 4] =
                *(const float4*)(W + (size_t)(k0 + kk) * DD + n0 + nq * 4);
        }
        __syncthreads();
#pragma unroll
        for (int k = 0; k < 16; k++) {
            float4 ra = *(const float4*)&As[k][ty * 4];
            float4 rb = *(const float4*)&Bs[k][tx * 4];
            float a_[4] = {ra.x, ra.y, ra.z, ra.w};
            float b_[4] = {rb.x, rb.y, rb.z, rb.w};
#pragma unroll
            for (int i = 0; i < 4; i++)
#pragma unroll
                for (int j = 0; j < 4; j++)
                    acc[i][j] = fmaf(a_[i], b_[j], acc[i][j]);
        }
        __syncthreads();
    }

#pragma unroll
    for (int i = 0; i < 4; i++) {
        int m = m0 + ty * 4 + i;
        int b = m >> 11, s = m & (SS_ - 1);
#pragma unroll
        for (int j = 0; j < 4; j++) {
            int n = n0 + tx * 4 + j;
            int h = n >> 6, dh = n & 63;
            Out[(((size_t)(b * HH + h)) * SS_ + s) * HD + dh] = acc[i][j] + bias[n];
        }
    }
}

// ============================================================================
// NEW: split q, k (fp32 -> bf16 hi/lo)
// ============================================================================
__global__ __launch_bounds__(256) void split_qk_kernel()
{
    size_t i = (size_t)blockIdx.x * 256 + threadIdx.x;
    if (i < (size_t)BH * SS_ * HD) {
        float q = g_q[i];
        __nv_bfloat16 qh = __float2bfloat16(q);
        g_qh[i] = qh;
        g_ql[i] = __float2bfloat16(q - __bfloat162float(qh));
        float k = g_k[i];
        __nv_bfloat16 kh = __float2bfloat16(k);
        g_kh[i] = kh;
        g_kl[i] = __float2bfloat16(k - __bfloat162float(kh));
    }
}

// ============================================================================
// NEW: scores via mma.sync bf16 3-term split emulation.
// Per (bh): S[q,k] = (Q[q,:] . K[k,:]) / 8, fp32 out to g_p.
// CTA tile 64x64, K=64 single load. 256 threads = 8 warps (4x2),
// warp tile 16(m) x 32(n).
// ============================================================================
__device__ __forceinline__ uint32_t smem_u32(const void* p) {
    uint32_t a;
    asm("{ .reg .u64 t; cvta.to.shared.u64 t, %1; cvt.u32.u64 %0, t; }" : "=r"(a) : "l"(p));
    return a;
}

__device__ __forceinline__ void ldsm4(uint32_t* r, uint32_t addr) {
    asm volatile("ldmatrix.sync.aligned.m8n8.x4.shared.b16 {%0,%1,%2,%3}, [%4];"
                 : "=r"(r[0]), "=r"(r[1]), "=r"(r[2]), "=r"(r[3]) : "r"(addr));
}

__device__ __forceinline__ void mma16816(float* d, const uint32_t* a, const uint32_t* b) {
    asm volatile(
        "mma.sync.aligned.m16n8k16.row.col.f32.bf16.bf16.f32 "
        "{%0,%1,%2,%3}, {%4,%5,%6,%7}, {%8,%9}, {%0,%1,%2,%3};"
        : "+f"(d[0]), "+f"(d[1]), "+f"(d[2]), "+f"(d[3])
        : "r"(a[0]), "r"(a[1]), "r"(a[2]), "r"(a[3]), "r"(b[0]), "r"(b[1]));
}

#define LDSB 72   // bf16 elements per smem row (144B, 16B-aligned rows)

__global__ __launch_bounds__(256) void scores_mma_kernel()
{
    __shared__ __align__(16) __nv_bfloat16 Ah[64][LDSB];
    __shared__ __align__(16) __nv_bfloat16 Al[64][LDSB];
    __shared__ __align__(16) __nv_bfloat16 Bh[64][LDSB];
    __shared__ __align__(16) __nv_bfloat16 Bl[64][LDSB];

    const int bh = blockIdx.z;
    const int m0 = blockIdx.x * 64;
    const int n0 = blockIdx.y * 64;
    const int tid = threadIdx.x;
    const int wid = tid >> 5;
    const int lane = tid & 31;

    const __nv_bfloat16* Qh = g_qh + (size_t)bh * SS_ * HD;
    const __nv_bfloat16* Ql = g_ql + (size_t)bh * SS_ * HD;
    const __nv_bfloat16* Kh = g_kh + (size_t)bh * SS_ * HD;
    const __nv_bfloat16* Kl = g_kl + (size_t)bh * SS_ * HD;

    // fill: 4 arrays x 64 rows x 8 uint4 (64 bf16) = 2048 chunks, 8 per thread
    for (int idx = tid; idx < 2048; idx += 256) {
        int c = idx & 7;             // uint4 within row (8 bf16 each)
        int r = (idx >> 3) & 63;     // row
        int sel = idx >> 9;          // 0:Ah 1:Al 2:Bh 3:Bl
        const __nv_bfloat16* src;
        __nv_bfloat16* dst;
        if (sel == 0)      { src = Qh + (size_t)(m0 + r) * HD; dst = &Ah[r][0]; }
        else if (sel == 1) { src = Ql + (size_t)(m0 + r) * HD; dst = &Al[r][0]; }
        else if (sel == 2) { src = Kh + (size_t)(n0 + r) * HD; dst = &Bh[r][0]; }
        else               { src = Kl + (size_t)(n0 + r) * HD; dst = &Bl[r][0]; }
        uint4 val = ((const uint4*)src)[c];
        *(uint4*)(dst + c * 8) = val;
    }
    __syncthreads();

    const uint32_t sAh = smem_u32(&Ah[0][0]);
    const uint32_t sAl = smem_u32(&Al[0][0]);
    const uint32_t sBh = smem_u32(&Bh[0][0]);
    const uint32_t sBl = smem_u32(&Bl[0][0]);

    // warp layout: wy = wid>>1 (0-3) -> m rows wy*16 ; wx = wid&1 -> n cols wx*32
    const int wy = wid >> 1;
    const int wx = wid & 1;

    // ldmatrix lane address components
    const int a_r = lane & 15;
    const int a_c = (lane >> 4) << 3;
    const int b_r = ((lane >> 4) << 3) | (lane & 7);
    const int b_c = ((lane >> 3) & 1) << 3;

    float acc[4][4] = {};   // [n8-tile][4]

#pragma unroll
    for (int ks = 0; ks < 4; ks++) {
        uint32_t afh[4], afl[4];
        {
            uint32_t off = (uint32_t)((wy * 16 + a_r) * LDSB + ks * 16 + a_c) * 2u;
            ldsm4(afh, sAh + off);
            ldsm4(afl, sAl + off);
        }
        uint32_t bfh[2][4], bfl[2][4];
#pragma unroll
        for (int jn = 0; jn < 2; jn++) {
            uint32_t off = (uint32_t)((wx * 32 + jn * 16 + b_r) * LDSB + ks * 16 + b_c) * 2u;
            ldsm4(bfh[jn], sBh + off);
            ldsm4(bfl[jn], sBl + off);
        }
#pragma unroll
        for (int jn = 0; jn < 2; jn++)
#pragma unroll
            for (int hf = 0; hf < 2; hf++) {
                int j8 = jn * 2 + hf;
                mma16816(acc[j8], afh, &bfh[jn][hf * 2]);
                mma16816(acc[j8], afh, &bfl[jn][hf * 2]);
                mma16816(acc[j8], afl, &bfh[jn][hf * 2]);
            }
    }

    // epilogue: fp32 * 0.125 -> g_p
    float* __restrict__ Sb = g_p + (size_t)bh * SSQ;
    const int er = lane >> 2;
    const int ec = (lane & 3) * 2;
#pragma unroll
    for (int j8 = 0; j8 < 4; j8++) {
        int m = m0 + wy * 16 + er;
        int n = n0 + wx * 32 + j8 * 8 + ec;
        float2 v0 = make_float2(acc[j8][0] * 0.125f, acc[j8][1] * 0.125f);
        float2 v1 = make_float2(acc[j8][2] * 0.125f, acc[j8][3] * 0.125f);
        *(float2*)(Sb + (size_t)m * SS_ + n) = v0;
        *(float2*)(Sb + (size_t)(m + 8) * SS_ + n) = v1;
    }
}

// ============================================================================
// Row softmax in place over g_p (UNCHANGED from R1)
// ============================================================================
__global__ __launch_bounds__(256) void softmax_kernel()
{
    float* __restrict__ p = g_p + (size_t)blockIdx.x * SS_;
    const int tid = threadIdx.x;
    __shared__ float sm[8];

    float v[8];
    float mx = -3.4e38f;
#pragma unroll
    for (int i = 0; i < 8; i++) { v[i] = p[tid + i * 256]; mx = fmaxf(mx, v[i]); }
#pragma unroll
    for (int o = 16; o; o >>= 1) mx = fmaxf(mx, __shfl_xor_sync(~0u, mx, o));
    if ((tid & 31) == 0) sm[tid >> 5] = mx;
    __syncthreads();
    mx = sm[0];
#pragma unroll
    for (int i = 1; i < 8; i++) mx = fmaxf(mx, sm[i]);
    __syncthreads();

    float sum = 0.f;
#pragma unroll
    for (int i = 0; i < 8; i++) { v[i] = __expf(v[i] - mx); sum += v[i]; }
#pragma unroll
    for (int o = 16; o; o >>= 1) sum += __shfl_xor_sync(~0u, sum, o);
    if ((tid & 31) == 0) sm[tid >> 5] = sum;
    __syncthreads();
    float total = 0.f;
#pragma unroll
    for (int i = 0; i < 8; i++) total += sm[i];

    float inv = 1.0f / total;
#pragma unroll
    for (int i = 0; i < 8; i++) p[tid + i * 256] = v[i] * inv;
}

// ============================================================================
// attn_mean (UNCHANGED from R1)
// ============================================================================
__global__ __launch_bounds__(256) void mean_kernel(float* __restrict__ attn_mean)
{
    size_t i4 = (size_t)blockIdx.x * 256 + threadIdx.x;
    size_t per_b = SSQ / 4;
    size_t b = i4 / per_b;
    size_t r4 = i4 - b * per_b;
    const float4* base = (const float4*)g_p + b * (size_t)HH * per_b + r4;
    float4 acc = {0.f, 0.f, 0.f, 0.f};
#pragma unroll
    for (int h = 0; h < HH; h++) {
        float4 t = base[(size_t)h * per_b];
        acc.x += t.x; acc.y += t.y; acc.z += t.z; acc.w += t.w;
    }
    const float inv = 1.0f / 16.0f;
    float4 o = {acc.x * inv, acc.y * inv, acc.z * inv, acc.w * inv};
    ((float4*)attn_mean)[i4] = o;
}

// ============================================================================
// ctx = P @ V (UNCHANGED from R1)
// ============================================================================
__global__ __launch_bounds__(256) void ctx_kernel()
{
    __shared__ __align__(16) float As[32][68];
    __shared__ __align__(16) float Bs[32][68];

    const int bh = blockIdx.y;
    const int m0 = blockIdx.x * 64;
    const float* __restrict__ P = g_p + (size_t)bh * SSQ;
    const float* __restrict__ V = g_v + (size_t)bh * SS_ * HD;

    const int tid = threadIdx.x;
    const int tx = tid & 15, ty = tid >> 4;
    float acc[4][4] = {};

    for (int k0 = 0; k0 < SS_; k0 += 32) {
#pragma unroll
        for (int r = 0; r < 2; r++) {
            int id = tid + r * 256;
            int m = id >> 3, kq = id & 7;
            float4 a = *(const float4*)(P + (size_t)(m0 + m) * SS_ + k0 + kq * 4);
            As[kq * 4 + 0][m] = a.x; As[kq * 4 + 1][m] = a.y;
            As[kq * 4 + 2][m] = a.z; As[kq * 4 + 3][m] = a.w;
            int kk = id >> 4, nq = id & 15;
            *(float4*)&Bs[kk][nq * 4] =
                *(const float4*)(V + (size_t)(k0 + kk) * HD + nq * 4);
        }
        __syncthreads();
#pragma unroll
        for (int k = 0; k < 32; k++) {
            float4 ra = *(const float4*)&As[k][ty * 4];
            float4 rb = *(const float4*)&Bs[k][tx * 4];
            float a_[4] = {ra.x, ra.y, ra.z, ra.w};
            float b_[4] = {rb.x, rb.y, rb.z, rb.w};
#pragma unroll
            for (int i = 0; i < 4; i++)
#pragma unroll
                for (int j = 0; j < 4; j++)
                    acc[i][j] = fmaf(a_[i], b_[j], acc[i][j]);
        }
        __syncthreads();
    }

    float* __restrict__ C = g_ctx + (size_t)bh * SS_ * HD;
#pragma unroll
    for (int i = 0; i < 4; i++) {
        size_t row = (size_t)(m0 + ty * 4 + i) * HD;
#pragma unroll
        for (int j = 0; j < 4; j++)
            C[row + tx * 4 + j] = acc[i][j];
    }
}

// ============================================================================
// out = Ctx2 @ Wo + bo (UNCHANGED from R1)
// ============================================================================
__global__ __launch_bounds__(256) void out_kernel(
    const float* __restrict__ Wo, const float* __restrict__ bo,
    float* __restrict__ out)
{
    __shared__ __align__(16) float As[16][68];
    __shared__ __align__(16) float Bs[16][68];

    const int m0 = blockIdx.x * 64;
    const int n0 = blockIdx.y * 64;
    const int tid = threadIdx.x;
    const int tx = tid & 15, ty = tid >> 4;

    float acc[4][4] = {};

    for (int k0 = 0; k0 < DD; k0 += 16) {
        {
            int m = tid >> 2, kq = tid & 3;
            int mm = m0 + m;
            int b = mm >> 11, s = mm & (SS_ - 1);
            int h = k0 >> 6, dh = k0 & 63;
            const float* arow =
                g_ctx + (((size_t)(b * HH + h)) * SS_ + s) * HD + dh;
            float4 a = *(const float4*)(arow + kq * 4);
            As[kq * 4 + 0][m] = a.x; As[kq * 4 + 1][m] = a.y;
            As[kq * 4 + 2][m] = a.z; As[kq * 4 + 3][m] = a.w;
        }
        {
            int kk = tid >> 4, nq = tid & 15;
            *(float4*)&Bs[kk][nq * 4] =
                *(const float4*)(Wo + (size_t)(k0 + kk) * DD + n0 + nq * 4);
        }
        __syncthreads();
#pragma unroll
        for (int k = 0; k < 16; k++) {
            float4 ra = *(const float4*)&As[k][ty * 4];
            float4 rb = *(const float4*)&Bs[k][tx * 4];
            float a_[4] = {ra.x, ra.y, ra.z, ra.w};
            float b_[4] = {rb.x, rb.y, rb.z, rb.w};
#pragma unroll
            for (int i = 0; i < 4; i++)
#pragma unroll
                for (int j = 0; j < 4; j++)
                    acc[i][j] = fmaf(a_[i], b_[j], acc[i][j]);
        }
        __syncthreads();
    }

#pragma unroll
    for (int i = 0; i < 4; i++) {
        size_t m = (size_t)(m0 + ty * 4 + i);
#pragma unroll
        for (int j = 0; j < 4; j++) {
            int n = n0 + tx * 4 + j;
            out[m * DD + n] = acc[i][j] + bo[n];
        }
    }
}

// ============================================================================
extern "C" void kernel_launch(void* const* d_in, const int* in_sizes, int n_in,
                              void* d_out, int out_size)
{
    const float* x  = (const float*)d_in[0];
    const float* Wq = (const float*)d_in[1];
    const float* bq = (const float*)d_in[2];
    const float* Wk = (const float*)d_in[3];
    const float* bk = (const float*)d_in[4];
    const float* Wv = (const float*)d_in[5];
    const float* bv = (const float*)d_in[6];
    const float* Wo = (const float*)d_in[7];
    const float* bo = (const float*)d_in[8];

    float* out = (float*)d_out;                        // [B,S,D]
    float* attn_mean = out + (size_t)BB * SS_ * DD;    // [B,S,S]

    dim3 gp(M_TOT / 64, DD / 64);        // (64,16)
    proj_kernel<<<gp, 256>>>(x, Wq, bq, 0);
    proj_kernel<<<gp, 256>>>(x, Wk, bk, 1);
    proj_kernel<<<gp, 256>>>(x, Wv, bv, 2);

    // split q/k to bf16 hi/lo, then tensor-core scores
    split_qk_kernel<<<(unsigned)(((size_t)BH * SS_ * HD + 255) / 256), 256>>>();
    dim3 gs(SS_ / 64, SS_ / 64, BH);     // (32,32,32)
    scores_mma_kernel<<<gs, 256>>>();

    softmax_kernel<<<BH * SS_, 256>>>(); // 65536 rows

    mean_kernel<<<(unsigned)((size_t)BB * SSQ / 4 / 256), 256>>>(attn_mean);

    dim3 gc(SS_ / 64, BH);               // (32,32)
    ctx_kernel<<<gc, 256>>>();

    out_kernel<<<gp, 256>>>(Wo, bo, out);
}

// round 6
// speedup vs baseline: 1.2578x; 1.0637x over previous
#include <cuda_runtime.h>
#include <cuda_bf16.h>
#include <cstdint>

#define BB 2
#define SS_ 2048
#define DD 1024
#define HH 16
#define HD 64
#define M_TOT (BB * SS_)        // 4096
#define BH (BB * HH)            // 32
#define SSQ ((size_t)SS_ * SS_) // 4194304 per (b,h)

// -------- scratch (device globals; ~650 MB total, proven range) --------
__device__ float g_q[(size_t)BH * SS_ * HD];        // 16 MB
__device__ float g_k[(size_t)BH * SS_ * HD];        // 16 MB
__device__ float g_v[(size_t)BH * SS_ * HD];        // 16 MB
__device__ float g_ctx[(size_t)BH * SS_ * HD];      // 16 MB
__device__ __align__(256) __nv_bfloat16 g_qh[(size_t)BH * SS_ * HD];  // 8 MB
__device__ __align__(256) __nv_bfloat16 g_ql[(size_t)BH * SS_ * HD];
__device__ __align__(256) __nv_bfloat16 g_kh[(size_t)BH * SS_ * HD];
__device__ __align__(256) __nv_bfloat16 g_kl[(size_t)BH * SS_ * HD];
__device__ __align__(256) __nv_bfloat16 g_vth[(size_t)BH * HD * SS_]; // V^T hi [bh,dh,s]
__device__ __align__(256) __nv_bfloat16 g_vtl[(size_t)BH * HD * SS_];
__device__ __align__(256) __nv_bfloat16 g_ph[(size_t)BH * SSQ];       // 268 MB scores->probs hi
__device__ __align__(256) __nv_bfloat16 g_pl[(size_t)BH * SSQ];       // 268 MB scores->probs lo

// ======================= small helpers ======================================
__device__ __forceinline__ void split2(float v, __nv_bfloat16& hi, __nv_bfloat16& lo) {
    hi = __float2bfloat16(v);
    lo = __float2bfloat16(v - __bfloat162float(hi));
}

__device__ __forceinline__ uint32_t smem_u32(const void* p) {
    uint32_t a;
    asm("{ .reg .u64 t; cvta.to.shared.u64 t, %1; cvt.u32.u64 %0, t; }" : "=r"(a) : "l"(p));
    return a;
}

__device__ __forceinline__ void ldsm4(uint32_t* r, uint32_t addr) {
    asm volatile("ldmatrix.sync.aligned.m8n8.x4.shared.b16 {%0,%1,%2,%3}, [%4];"
                 : "=r"(r[0]), "=r"(r[1]), "=r"(r[2]), "=r"(r[3]) : "r"(addr));
}

__device__ __forceinline__ void mma16816(float* d, const uint32_t* a, const uint32_t* b) {
    asm volatile(
        "mma.sync.aligned.m16n8k16.row.col.f32.bf16.bf16.f32 "
        "{%0,%1,%2,%3}, {%4,%5,%6,%7}, {%8,%9}, {%0,%1,%2,%3};"
        : "+f"(d[0]), "+f"(d[1]), "+f"(d[2]), "+f"(d[3])
        : "r"(a[0]), "r"(a[1]), "r"(a[2]), "r"(a[3]), "r"(b[0]), "r"(b[1]));
}

// ============================================================================
// Projection GEMM (UNCHANGED, proven)
// ============================================================================
__global__ __launch_bounds__(256) void proj_kernel(
    const float* __restrict__ X, const float* __restrict__ W,
    const float* __restrict__ bias, int which)
{
    __shared__ __align__(16) float As[16][68];
    __shared__ __align__(16) float Bs[16][68];
    float* __restrict__ Out = (which == 0) ? g_q : (which == 1) ? g_k : g_v;

    const int m0 = blockIdx.x * 64;
    const int n0 = blockIdx.y * 64;
    const int tid = threadIdx.x;
    const int tx = tid & 15, ty = tid >> 4;

    float acc[4][4] = {};

    for (int k0 = 0; k0 < DD; k0 += 16) {
        {
            int m = tid >> 2, kq = tid & 3;
            float4 a = *(const float4*)(X + (size_t)(m0 + m) * DD + k0 + kq * 4);
            As[kq * 4 + 0][m] = a.x; As[kq * 4 + 1][m] = a.y;
            As[kq * 4 + 2][m] = a.z; As[kq * 4 + 3][m] = a.w;
        }
        {
            int kk = tid >> 4, nq = tid & 15;
            *(float4*)&Bs[kk][nq * 4] =
                *(const float4*)(W + (size_t)(k0 + kk) * DD + n0 + nq * 4);
        }
        __syncthreads();
#pragma unroll
        for (int k = 0; k < 16; k++) {
            float4 ra = *(const float4*)&As[k][ty * 4];
            float4 rb = *(const float4*)&Bs[k][tx * 4];
            float a_[4] = {ra.x, ra.y, ra.z, ra.w};
            float b_[4] = {rb.x, rb.y, rb.z, rb.w};
#pragma unroll
            for (int i = 0; i < 4; i++)
#pragma unroll
                for (int j = 0; j < 4; j++)
                    acc[i][j] = fmaf(a_[i], b_[j], acc[i][j]);
        }
        __syncthreads();
    }

#pragma unroll
    for (int i = 0; i < 4; i++) {
        int m = m0 + ty * 4 + i;
        int b = m >> 11, s = m & (SS_ - 1);
#pragma unroll
        for (int j = 0; j < 4; j++) {
            int n = n0 + tx * 4 + j;
            int h = n >> 6, dh = n & 63;
            Out[(((size_t)(b * HH + h)) * SS_ + s) * HD + dh] = acc[i][j] + bias[n];
        }
    }
}

// ============================================================================
// split q, k (fp32 -> bf16 hi/lo)  (UNCHANGED, proven)
// ============================================================================
__global__ __launch_bounds__(256) void split_qk_kernel()
{
    size_t i = (size_t)blockIdx.x * 256 + threadIdx.x;
    if (i < (size_t)BH * SS_ * HD) {
        float q = g_q[i];
        __nv_bfloat16 qh = __float2bfloat16(q);
        g_qh[i] = qh;
        g_ql[i] = __float2bfloat16(q - __bfloat162float(qh));
        float k = g_k[i];
        __nv_bfloat16 kh = __float2bfloat16(k);
        g_kh[i] = kh;
        g_kl[i] = __float2bfloat16(k - __bfloat162float(kh));
    }
}

// ============================================================================
// NEW: V [bh, s, dh] fp32 -> V^T [bh, dh, s] bf16 hi/lo (32x32 smem transpose)
// grid (S/32, HD/32, BH), block (32, 8)
// ============================================================================
__global__ __launch_bounds__(256) void split_v_kernel()
{
    __shared__ __align__(16) float t[32][33];
    const int tx = threadIdx.x, ty = threadIdx.y;
    const int s0 = blockIdx.x * 32;
    const int d0 = blockIdx.y * 32;
    const int bh = blockIdx.z;
    const float* __restrict__ V = g_v + (size_t)bh * SS_ * HD;

#pragma unroll
    for (int j = 0; j < 4; j++)
        t[ty + 8 * j][tx] = V[(size_t)(s0 + ty + 8 * j) * HD + d0 + tx];
    __syncthreads();

    __nv_bfloat16* __restrict__ th = g_vth + (size_t)bh * HD * SS_;
    __nv_bfloat16* __restrict__ tl = g_vtl + (size_t)bh * HD * SS_;
#pragma unroll
    for (int j = 0; j < 4; j++) {
        float v = t[tx][ty + 8 * j];                 // = V[s0+tx][d0+ty+8j]
        __nv_bfloat16 hi, lo; split2(v, hi, lo);
        size_t di = (size_t)(d0 + ty + 8 * j) * SS_ + s0 + tx;
        th[di] = hi; tl[di] = lo;
    }
}

#define LDSB 72   // bf16 elements per smem row (144B)

// ============================================================================
// scores via mma (validated core); epilogue now writes bf16 hi/lo to g_ph/g_pl
// ============================================================================
__global__ __launch_bounds__(256) void scores_mma_kernel()
{
    __shared__ __align__(16) __nv_bfloat16 Ah[64][LDSB];
    __shared__ __align__(16) __nv_bfloat16 Al[64][LDSB];
    __shared__ __align__(16) __nv_bfloat16 Bh[64][LDSB];
    __shared__ __align__(16) __nv_bfloat16 Bl[64][LDSB];

    const int bh = blockIdx.z;
    const int m0 = blockIdx.x * 64;
    const int n0 = blockIdx.y * 64;
    const int tid = threadIdx.x;
    const int wid = tid >> 5;
    const int lane = tid & 31;

    const __nv_bfloat16* Qh = g_qh + (size_t)bh * SS_ * HD;
    const __nv_bfloat16* Ql = g_ql + (size_t)bh * SS_ * HD;
    const __nv_bfloat16* Kh = g_kh + (size_t)bh * SS_ * HD;
    const __nv_bfloat16* Kl = g_kl + (size_t)bh * SS_ * HD;

    for (int idx = tid; idx < 2048; idx += 256) {
        int c = idx & 7;
        int r = (idx >> 3) & 63;
        int sel = idx >> 9;
        const __nv_bfloat16* src;
        __nv_bfloat16* dst;
        if (sel == 0)      { src = Qh + (size_t)(m0 + r) * HD; dst = &Ah[r][0]; }
        else if (sel == 1) { src = Ql + (size_t)(m0 + r) * HD; dst = &Al[r][0]; }
        else if (sel == 2) { src = Kh + (size_t)(n0 + r) * HD; dst = &Bh[r][0]; }
        else               { src = Kl + (size_t)(n0 + r) * HD; dst = &Bl[r][0]; }
        uint4 val = ((const uint4*)src)[c];
        *(uint4*)(dst + c * 8) = val;
    }
    __syncthreads();

    const uint32_t sAh = smem_u32(&Ah[0][0]);
    const uint32_t sAl = smem_u32(&Al[0][0]);
    const uint32_t sBh = smem_u32(&Bh[0][0]);
    const uint32_t sBl = smem_u32(&Bl[0][0]);

    const int wy = wid >> 1;
    const int wx = wid & 1;
    const int a_r = lane & 15;
    const int a_c = (lane >> 4) << 3;
    const int b_r = ((lane >> 4) << 3) | (lane & 7);
    const int b_c = ((lane >> 3) & 1) << 3;

    float acc[4][4] = {};

#pragma unroll
    for (int ks = 0; ks < 4; ks++) {
        uint32_t afh[4], afl[4];
        {
            uint32_t off = (uint32_t)((wy * 16 + a_r) * LDSB + ks * 16 + a_c) * 2u;
            ldsm4(afh, sAh + off);
            ldsm4(afl, sAl + off);
        }
        uint32_t bfh[2][4], bfl[2][4];
#pragma unroll
        for (int jn = 0; jn < 2; jn++) {
            uint32_t off = (uint32_t)((wx * 32 + jn * 16 + b_r) * LDSB + ks * 16 + b_c) * 2u;
            ldsm4(bfh[jn], sBh + off);
            ldsm4(bfl[jn], sBl + off);
        }
#pragma unroll
        for (int jn = 0; jn < 2; jn++)
#pragma unroll
            for (int hf = 0; hf < 2; hf++) {
                int j8 = jn * 2 + hf;
                mma16816(acc[j8], afh, &bfh[jn][hf * 2]);
                mma16816(acc[j8], afh, &bfl[jn][hf * 2]);
                mma16816(acc[j8], afl, &bfh[jn][hf * 2]);
            }
    }

    // epilogue: *0.125, split to bf16 hi/lo pairs
    __nv_bfloat16* __restrict__ Ph = g_ph + (size_t)bh * SSQ;
    __nv_bfloat16* __restrict__ Pl = g_pl + (size_t)bh * SSQ;
    const int er = lane >> 2;
    const int ec = (lane & 3) * 2;
#pragma unroll
    for (int j8 = 0; j8 < 4; j8++) {
        int m = m0 + wy * 16 + er;
        int n = n0 + wx * 32 + j8 * 8 + ec;
#pragma unroll
        for (int half = 0; half < 2; half++) {
            float v0 = acc[j8][half * 2 + 0] * 0.125f;
            float v1 = acc[j8][half * 2 + 1] * 0.125f;
            __nv_bfloat16 h0, l0, h1, l1;
            split2(v0, h0, l0);
            split2(v1, h1, l1);
            size_t di = (size_t)(m + half * 8) * SS_ + n;
            *(__nv_bfloat162*)(Ph + di) = __halves2bfloat162(h0, h1);
            *(__nv_bfloat162*)(Pl + di) = __halves2bfloat162(l0, l1);
        }
    }
}

// ============================================================================
// NEW: fused softmax + head-mean. One block per (b,q); loops 16 heads.
// Reads score hi+lo, writes prob hi/lo in place (block-local rows).
// ============================================================================
__global__ __launch_bounds__(256) void softmax_mean_kernel(float* __restrict__ attn_mean)
{
    const int bq = blockIdx.x;
    const int b = bq >> 11;
    const int q = bq & (SS_ - 1);
    const int tid = threadIdx.x;
    __shared__ float sm[8];

    float macc[8] = {};

    for (int h = 0; h < HH; h++) {
        const size_t row = ((size_t)(b * HH + h) * SS_ + q) * SS_;

        float v[8];
        float mx = -3.4e38f;
#pragma unroll
        for (int i = 0; i < 8; i++) {
            size_t idx = row + tid + i * 256;
            v[i] = __bfloat162float(g_ph[idx]) + __bfloat162float(g_pl[idx]);
            mx = fmaxf(mx, v[i]);
        }
#pragma unroll
        for (int o = 16; o; o >>= 1) mx = fmaxf(mx, __shfl_xor_sync(~0u, mx, o));
        if ((tid & 31) == 0) sm[tid >> 5] = mx;
        __syncthreads();
        mx = sm[0];
#pragma unroll
        for (int i = 1; i < 8; i++) mx = fmaxf(mx, sm[i]);
        __syncthreads();

        float sum = 0.f;
#pragma unroll
        for (int i = 0; i < 8; i++) { v[i] = __expf(v[i] - mx); sum += v[i]; }
#pragma unroll
        for (int o = 16; o; o >>= 1) sum += __shfl_xor_sync(~0u, sum, o);
        if ((tid & 31) == 0) sm[tid >> 5] = sum;
        __syncthreads();
        float total = 0.f;
#pragma unroll
        for (int i = 0; i < 8; i++) total += sm[i];
        __syncthreads();

        const float inv = 1.0f / total;
#pragma unroll
        for (int i = 0; i < 8; i++) {
            float pv = v[i] * inv;
            macc[i] += pv;
            __nv_bfloat16 hi, lo; split2(pv, hi, lo);
            size_t idx = row + tid + i * 256;
            g_ph[idx] = hi;
            g_pl[idx] = lo;
        }
    }

    const float inv16 = 1.0f / 16.0f;
    float* dst = attn_mean + (size_t)bq * SS_;
#pragma unroll
    for (int i = 0; i < 8; i++) dst[tid + i * 256] = macc[i] * inv16;
}

// ============================================================================
// NEW: ctx = P @ V via mma. Per bh: M=2048, N=64, K=2048 (BK=64 x 32 iters).
// A = P hi/lo [m, k] (k-contig), B = V^T hi/lo [dh, s] (k-contig).
// grid (32, 32[bh]); same 8-warp layout as scores. fp32 out to g_ctx.
// ============================================================================
__global__ __launch_bounds__(256) void ctx_mma_kernel()
{
    __shared__ __align__(16) __nv_bfloat16 Ah[64][LDSB];
    __shared__ __align__(16) __nv_bfloat16 Al[64][LDSB];
    __shared__ __align__(16) __nv_bfloat16 Bh[64][LDSB];
    __shared__ __align__(16) __nv_bfloat16 Bl[64][LDSB];

    const int bh = blockIdx.y;
    const int m0 = blockIdx.x * 64;
    const int tid = threadIdx.x;
    const int wid = tid >> 5;
    const int lane = tid & 31;

    const __nv_bfloat16* Ph = g_ph + (size_t)bh * SSQ;
    const __nv_bfloat16* Pl = g_pl + (size_t)bh * SSQ;
    const __nv_bfloat16* Vh = g_vth + (size_t)bh * HD * SS_;
    const __nv_bfloat16* Vl = g_vtl + (size_t)bh * HD * SS_;

    const uint32_t sAh = smem_u32(&Ah[0][0]);
    const uint32_t sAl = smem_u32(&Al[0][0]);
    const uint32_t sBh = smem_u32(&Bh[0][0]);
    const uint32_t sBl = smem_u32(&Bl[0][0]);

    const int wy = wid >> 1;
    const int wx = wid & 1;
    const int a_r = lane & 15;
    const int a_c = (lane >> 4) << 3;
    const int b_r = ((lane >> 4) << 3) | (lane & 7);
    const int b_c = ((lane >> 3) & 1) << 3;

    float acc[4][4] = {};

    for (int it = 0; it < 32; ++it) {
        const int k0 = it * 64;
        for (int idx = tid; idx < 2048; idx += 256) {
            int c = idx & 7;
            int r = (idx >> 3) & 63;
            int sel = idx >> 9;
            const __nv_bfloat16* src;
            __nv_bfloat16* dst;
            if (sel == 0)      { src = Ph + (size_t)(m0 + r) * SS_ + k0; dst = &Ah[r][0]; }
            else if (sel == 1) { src = Pl + (size_t)(m0 + r) * SS_ + k0; dst = &Al[r][0]; }
            else if (sel == 2) { src = Vh + (size_t)r * SS_ + k0;        dst = &Bh[r][0]; }
            else               { src = Vl + (size_t)r * SS_ + k0;        dst = &Bl[r][0]; }
            uint4 val = ((const uint4*)src)[c];
            *(uint4*)(dst + c * 8) = val;
        }
        __syncthreads();

#pragma unroll
        for (int ks = 0; ks < 4; ks++) {
            uint32_t afh[4], afl[4];
            {
                uint32_t off = (uint32_t)((wy * 16 + a_r) * LDSB + ks * 16 + a_c) * 2u;
                ldsm4(afh, sAh + off);
                ldsm4(afl, sAl + off);
            }
            uint32_t bfh[2][4], bfl[2][4];
#pragma unroll
            for (int jn = 0; jn < 2; jn++) {
                uint32_t off = (uint32_t)((wx * 32 + jn * 16 + b_r) * LDSB + ks * 16 + b_c) * 2u;
                ldsm4(bfh[jn], sBh + off);
                ldsm4(bfl[jn], sBl + off);
            }
#pragma unroll
            for (int jn = 0; jn < 2; jn++)
#pragma unroll
                for (int hf = 0; hf < 2; hf++) {
                    int j8 = jn * 2 + hf;
                    mma16816(acc[j8], afh, &bfh[jn][hf * 2]);
                    mma16816(acc[j8], afh, &bfl[jn][hf * 2]);
                    mma16816(acc[j8], afl, &bfh[jn][hf * 2]);
                }
        }
        __syncthreads();
    }

    float* __restrict__ C = g_ctx + (size_t)bh * SS_ * HD;
    const int er = lane >> 2;
    const int ec = (lane & 3) * 2;
#pragma unroll
    for (int j8 = 0; j8 < 4; j8++) {
        int m = m0 + wy * 16 + er;
        int n = wx * 32 + j8 * 8 + ec;            // dh 0..63
        float2 v0 = make_float2(acc[j8][0], acc[j8][1]);
        float2 v1 = make_float2(acc[j8][2], acc[j8][3]);
        *(float2*)(C + (size_t)m * HD + n) = v0;
        *(float2*)(C + (size_t)(m + 8) * HD + n) = v1;
    }
}

// ============================================================================
// out = Ctx2 @ Wo + bo (UNCHANGED, proven)
// ============================================================================
__global__ __launch_bounds__(256) void out_kernel(
    const float* __restrict__ Wo, const float* __restrict__ bo,
    float* __restrict__ out)
{
    __shared__ __align__(16) float As[16][68];
    __shared__ __align__(16) float Bs[16][68];

    const int m0 = blockIdx.x * 64;
    const int n0 = blockIdx.y * 64;
    const int tid = threadIdx.x;
    const int tx = tid & 15, ty = tid >> 4;

    float acc[4][4] = {};

    for (int k0 = 0; k0 < DD; k0 += 16) {
        {
            int m = tid >> 2, kq = tid & 3;
            int mm = m0 + m;
            int b = mm >> 11, s = mm & (SS_ - 1);
            int h = k0 >> 6, dh = k0 & 63;
            const float* arow =
                g_ctx + (((size_t)(b * HH + h)) * SS_ + s) * HD + dh;
            float4 a = *(const float4*)(arow + kq * 4);
            As[kq * 4 + 0][m] = a.x; As[kq * 4 + 1][m] = a.y;
            As[kq * 4 + 2][m] = a.z; As[kq * 4 + 3][m] = a.w;
        }
        {
            int kk = tid >> 4, nq = tid & 15;
            *(float4*)&Bs[kk][nq * 4] =
                *(const float4*)(Wo + (size_t)(k0 + kk) * DD + n0 + nq * 4);
        }
        __syncthreads();
#pragma unroll
        for (int k = 0; k < 16; k++) {
            float4 ra = *(const float4*)&As[k][ty * 4];
            float4 rb = *(const float4*)&Bs[k][tx * 4];
            float a_[4] = {ra.x, ra.y, ra.z, ra.w};
            float b_[4] = {rb.x, rb.y, rb.z, rb.w};
#pragma unroll
            for (int i = 0; i < 4; i++)
#pragma unroll
                for (int j = 0; j < 4; j++)
                    acc[i][j] = fmaf(a_[i], b_[j], acc[i][j]);
        }
        __syncthreads();
    }

#pragma unroll
    for (int i = 0; i < 4; i++) {
        size_t m = (size_t)(m0 + ty * 4 + i);
#pragma unroll
        for (int j = 0; j < 4; j++) {
            int n = n0 + tx * 4 + j;
            out[m * DD + n] = acc[i][j] + bo[n];
        }
    }
}

// ============================================================================
extern "C" void kernel_launch(void* const* d_in, const int* in_sizes, int n_in,
                              void* d_out, int out_size)
{
    const float* x  = (const float*)d_in[0];
    const float* Wq = (const float*)d_in[1];
    const float* bq = (const float*)d_in[2];
    const float* Wk = (const float*)d_in[3];
    const float* bk = (const float*)d_in[4];
    const float* Wv = (const float*)d_in[5];
    const float* bv = (const float*)d_in[6];
    const float* Wo = (const float*)d_in[7];
    const float* bo = (const float*)d_in[8];

    float* out = (float*)d_out;                        // [B,S,D]
    float* attn_mean = out + (size_t)BB * SS_ * DD;    // [B,S,S]

    dim3 gp(M_TOT / 64, DD / 64);        // (64,16)
    proj_kernel<<<gp, 256>>>(x, Wq, bq, 0);
    proj_kernel<<<gp, 256>>>(x, Wk, bk, 1);
    proj_kernel<<<gp, 256>>>(x, Wv, bv, 2);

    split_qk_kernel<<<(unsigned)(((size_t)BH * SS_ * HD + 255) / 256), 256>>>();
    dim3 tv(32, 8), gv(SS_ / 32, HD / 32, BH);
    split_v_kernel<<<gv, tv>>>();

    dim3 gs(SS_ / 64, SS_ / 64, BH);     // (32,32,32)
    scores_mma_kernel<<<gs, 256>>>();

    softmax_mean_kernel<<<BB * SS_, 256>>>(attn_mean);

    dim3 gc(SS_ / 64, BH);               // (32,32)
    ctx_mma_kernel<<<gc, 256>>>();

    out_kernel<<<gp, 256>>>(Wo, bo, out);
}

// round 8
// speedup vs baseline: 1.6587x; 1.3187x over previous
#include <cuda_runtime.h>
#include <cuda_bf16.h>
#include <cstdint>

#define BB 2
#define SS_ 2048
#define DD 1024
#define HH 16
#define HD 64
#define M_TOT (BB * SS_)        // 4096
#define BH (BB * HH)            // 32
#define SSQ ((size_t)SS_ * SS_) // 4194304 per (b,h)

// -------- scratch (~630 MB, proven range) --------
__device__ __align__(256) __nv_bfloat16 g_xh[(size_t)M_TOT * DD];     // 8 MB
__device__ __align__(256) __nv_bfloat16 g_xl[(size_t)M_TOT * DD];
__device__ __align__(256) __nv_bfloat16 g_wth[(size_t)4 * DD * DD];   // W^T hi (q,k,v,o)
__device__ __align__(256) __nv_bfloat16 g_wtl[(size_t)4 * DD * DD];
__device__ __align__(256) __nv_bfloat16 g_qh[(size_t)BH * SS_ * HD];
__device__ __align__(256) __nv_bfloat16 g_ql[(size_t)BH * SS_ * HD];
__device__ __align__(256) __nv_bfloat16 g_kh[(size_t)BH * SS_ * HD];
__device__ __align__(256) __nv_bfloat16 g_kl[(size_t)BH * SS_ * HD];
__device__ __align__(256) __nv_bfloat16 g_vth[(size_t)BH * HD * SS_]; // V^T [bh,dh,s]
__device__ __align__(256) __nv_bfloat16 g_vtl[(size_t)BH * HD * SS_];
__device__ __align__(256) __nv_bfloat16 g_ph[(size_t)BH * SSQ];       // 268 MB
__device__ __align__(256) __nv_bfloat16 g_pl[(size_t)BH * SSQ];       // 268 MB
__device__ __align__(256) __nv_bfloat16 g_ch[(size_t)M_TOT * DD];     // ctx [b,s,h*64+dh]
__device__ __align__(256) __nv_bfloat16 g_cl[(size_t)M_TOT * DD];

// ======================= small helpers ======================================
__device__ __forceinline__ void split2(float v, __nv_bfloat16& hi, __nv_bfloat16& lo) {
    hi = __float2bfloat16(v);
    lo = __float2bfloat16(v - __bfloat162float(hi));
}

__device__ __forceinline__ uint32_t smem_u32(const void* p) {
    uint32_t a;
    asm("{ .reg .u64 t; cvta.to.shared.u64 t, %1; cvt.u32.u64 %0, t; }" : "=r"(a) : "l"(p));
    return a;
}

__device__ __forceinline__ void ldsm4(uint32_t* r, uint32_t addr) {
    asm volatile("ldmatrix.sync.aligned.m8n8.x4.shared.b16 {%0,%1,%2,%3}, [%4];"
                 : "=r"(r[0]), "=r"(r[1]), "=r"(r[2]), "=r"(r[3]) : "r"(addr));
}

__device__ __forceinline__ void mma16816(float* d, const uint32_t* a, const uint32_t* b) {
    asm volatile(
        "mma.sync.aligned.m16n8k16.row.col.f32.bf16.bf16.f32 "
        "{%0,%1,%2,%3}, {%4,%5,%6,%7}, {%8,%9}, {%0,%1,%2,%3};"
        : "+f"(d[0]), "+f"(d[1]), "+f"(d[2]), "+f"(d[3])
        : "r"(a[0]), "r"(a[1]), "r"(a[2]), "r"(a[3]), "r"(b[0]), "r"(b[1]));
}

// ======================= prep: split x ======================================
__global__ __launch_bounds__(256) void split_x_kernel(const float* __restrict__ x)
{
    size_t i = (size_t)blockIdx.x * 256 + threadIdx.x;
    if (i < (size_t)M_TOT * DD) {
        __nv_bfloat16 h, l;
        split2(x[i], h, l);
        g_xh[i] = h; g_xl[i] = l;
    }
}

// ======================= prep: W[k,n] -> W^T[n,k] hi/lo =====================
__global__ __launch_bounds__(256) void transpose_split_w_kernel(
    const float* __restrict__ W, int which)
{
    __shared__ __align__(16) float t[32][33];
    const int tx = threadIdx.x, ty = threadIdx.y;   // (32,8)
    const int n0 = blockIdx.x * 32, k0 = blockIdx.y * 32;
    __nv_bfloat16* __restrict__ th = g_wth + (size_t)which * DD * DD;
    __nv_bfloat16* __restrict__ tl = g_wtl + (size_t)which * DD * DD;

#pragma unroll
    for (int j = 0; j < 4; j++)
        t[ty + 8 * j][tx] = W[(size_t)(k0 + ty + 8 * j) * DD + n0 + tx];
    __syncthreads();
#pragma unroll
    for (int j = 0; j < 4; j++) {
        float v = t[tx][ty + 8 * j];                 // = W[k0+tx][n0+ty+8j]
        __nv_bfloat16 hi, lo; split2(v, hi, lo);
        size_t di = (size_t)(n0 + ty + 8 * j) * DD + k0 + tx;
        th[di] = hi; tl[di] = lo;
    }
}

#define LDSB 72   // bf16 elements per smem row (144B)

// ============================================================================
// Generic 64x64-tile split-bf16 mma GEMM.  ALL global buffers resolved in
// DEVICE code via `mode` (host-passed __device__ addresses are invalid!).
// mode: 0 q = x @ Wq^T -> g_qh/g_ql [bh,s,dh]
//       1 k = x @ Wk^T -> g_kh/g_kl [bh,s,dh]
//       2 v = x @ Wv^T -> g_vth/g_vtl [bh,dh,s]
//       3 out = ctx @ Wo^T + bo -> fout (fp32)
// ============================================================================
__global__ __launch_bounds__(256) void gemm_mma_kernel(
    int mode, const float* __restrict__ bias, float* __restrict__ fout)
{
    __shared__ __align__(16) __nv_bfloat16 As_h[64][LDSB];
    __shared__ __align__(16) __nv_bfloat16 As_l[64][LDSB];
    __shared__ __align__(16) __nv_bfloat16 Bs_h[64][LDSB];
    __shared__ __align__(16) __nv_bfloat16 Bs_l[64][LDSB];

    // device-side pointer resolution
    const __nv_bfloat16* Ah = (mode == 3) ? g_ch : g_xh;
    const __nv_bfloat16* Al = (mode == 3) ? g_cl : g_xl;
    const __nv_bfloat16* Bh = g_wth + (size_t)mode * DD * DD;
    const __nv_bfloat16* Bl = g_wtl + (size_t)mode * DD * DD;
    const int K = DD;

    const int m0 = blockIdx.x * 64;
    const int n0 = blockIdx.y * 64;
    const int tid = threadIdx.x;
    const int wid = tid >> 5;
    const int lane = tid & 31;

    const uint32_t sAh = smem_u32(&As_h[0][0]);
    const uint32_t sAl = smem_u32(&As_l[0][0]);
    const uint32_t sBh = smem_u32(&Bs_h[0][0]);
    const uint32_t sBl = smem_u32(&Bs_l[0][0]);

    const int wy = wid >> 1;
    const int wx = wid & 1;
    const int a_r = lane & 15;
    const int a_c = (lane >> 4) << 3;
    const int b_r = ((lane >> 4) << 3) | (lane & 7);
    const int b_c = ((lane >> 3) & 1) << 3;

    float acc[4][4] = {};

    const int niter = K >> 6;
    for (int it = 0; it < niter; ++it) {
        const int k0 = it << 6;
        for (int idx = tid; idx < 2048; idx += 256) {
            int c = idx & 7;
            int r = (idx >> 3) & 63;
            int sel = idx >> 9;
            const __nv_bfloat16* src;
            __nv_bfloat16* dst;
            if (sel == 0)      { src = Ah + (size_t)(m0 + r) * K + k0; dst = &As_h[r][0]; }
            else if (sel == 1) { src = Al + (size_t)(m0 + r) * K + k0; dst = &As_l[r][0]; }
            else if (sel == 2) { src = Bh + (size_t)(n0 + r) * K + k0; dst = &Bs_h[r][0]; }
            else               { src = Bl + (size_t)(n0 + r) * K + k0; dst = &Bs_l[r][0]; }
            uint4 val = ((const uint4*)src)[c];
            *(uint4*)(dst + c * 8) = val;
        }
        __syncthreads();

#pragma unroll
        for (int ks = 0; ks < 4; ks++) {
            uint32_t afh[4], afl[4];
            {
                uint32_t off = (uint32_t)((wy * 16 + a_r) * LDSB + ks * 16 + a_c) * 2u;
                ldsm4(afh, sAh + off);
                ldsm4(afl, sAl + off);
            }
            uint32_t bfh[2][4], bfl[2][4];
#pragma unroll
            for (int jn = 0; jn < 2; jn++) {
                uint32_t off = (uint32_t)((wx * 32 + jn * 16 + b_r) * LDSB + ks * 16 + b_c) * 2u;
                ldsm4(bfh[jn], sBh + off);
                ldsm4(bfl[jn], sBl + off);
            }
#pragma unroll
            for (int jn = 0; jn < 2; jn++)
#pragma unroll
                for (int hf = 0; hf < 2; hf++) {
                    int j8 = jn * 2 + hf;
                    mma16816(acc[j8], afh, &bfh[jn][hf * 2]);
                    mma16816(acc[j8], afh, &bfl[jn][hf * 2]);
                    mma16816(acc[j8], afl, &bfh[jn][hf * 2]);
                }
        }
        __syncthreads();
    }

    // ---------------- epilogue --------------------------------------------
    const int er = lane >> 2;
    const int ec = (lane & 3) * 2;
#pragma unroll
    for (int j8 = 0; j8 < 4; j8++) {
#pragma unroll
        for (int half = 0; half < 2; half++) {
            int m = m0 + wy * 16 + er + half * 8;
            int n = n0 + wx * 32 + j8 * 8 + ec;
            float v0 = acc[j8][half * 2 + 0];
            float v1 = acc[j8][half * 2 + 1];
            if (mode == 3) {
                float2 o = make_float2(v0 + bias[n], v1 + bias[n + 1]);
                *(float2*)(fout + (size_t)m * DD + n) = o;
            } else {
                int b = m >> 11, s = m & (SS_ - 1);
                int h = n >> 6, dh = n & 63;
                __nv_bfloat16 h0, l0, h1, l1;
                split2(v0 + bias[n], h0, l0);
                split2(v1 + bias[n + 1], h1, l1);
                if (mode == 0) {
                    size_t di = (((size_t)(b * HH + h)) * SS_ + s) * HD + dh;
                    *(__nv_bfloat162*)(g_qh + di) = __halves2bfloat162(h0, h1);
                    *(__nv_bfloat162*)(g_ql + di) = __halves2bfloat162(l0, l1);
                } else if (mode == 1) {
                    size_t di = (((size_t)(b * HH + h)) * SS_ + s) * HD + dh;
                    *(__nv_bfloat162*)(g_kh + di) = __halves2bfloat162(h0, h1);
                    *(__nv_bfloat162*)(g_kl + di) = __halves2bfloat162(l0, l1);
                } else {   // mode == 2 : V^T [bh,dh,s]
                    size_t di = (((size_t)(b * HH + h)) * HD + dh) * SS_ + s;
                    g_vth[di] = h0; g_vtl[di] = l0;
                    g_vth[di + SS_] = h1; g_vtl[di + SS_] = l1;
                }
            }
        }
    }
}

// ============================================================================
// scores via mma (UNCHANGED, validated)
// ============================================================================
__global__ __launch_bounds__(256) void scores_mma_kernel()
{
    __shared__ __align__(16) __nv_bfloat16 Ah[64][LDSB];
    __shared__ __align__(16) __nv_bfloat16 Al[64][LDSB];
    __shared__ __align__(16) __nv_bfloat16 Bh[64][LDSB];
    __shared__ __align__(16) __nv_bfloat16 Bl[64][LDSB];

    const int bh = blockIdx.z;
    const int m0 = blockIdx.x * 64;
    const int n0 = blockIdx.y * 64;
    const int tid = threadIdx.x;
    const int wid = tid >> 5;
    const int lane = tid & 31;

    const __nv_bfloat16* Qh = g_qh + (size_t)bh * SS_ * HD;
    const __nv_bfloat16* Ql = g_ql + (size_t)bh * SS_ * HD;
    const __nv_bfloat16* Kh = g_kh + (size_t)bh * SS_ * HD;
    const __nv_bfloat16* Kl = g_kl + (size_t)bh * SS_ * HD;

    for (int idx = tid; idx < 2048; idx += 256) {
        int c = idx & 7;
        int r = (idx >> 3) & 63;
        int sel = idx >> 9;
        const __nv_bfloat16* src;
        __nv_bfloat16* dst;
        if (sel == 0)      { src = Qh + (size_t)(m0 + r) * HD; dst = &Ah[r][0]; }
        else if (sel == 1) { src = Ql + (size_t)(m0 + r) * HD; dst = &Al[r][0]; }
        else if (sel == 2) { src = Kh + (size_t)(n0 + r) * HD; dst = &Bh[r][0]; }
        else               { src = Kl + (size_t)(n0 + r) * HD; dst = &Bl[r][0]; }
        uint4 val = ((const uint4*)src)[c];
        *(uint4*)(dst + c * 8) = val;
    }
    __syncthreads();

    const uint32_t sAh = smem_u32(&Ah[0][0]);
    const uint32_t sAl = smem_u32(&Al[0][0]);
    const uint32_t sBh = smem_u32(&Bh[0][0]);
    const uint32_t sBl = smem_u32(&Bl[0][0]);

    const int wy = wid >> 1;
    const int wx = wid & 1;
    const int a_r = lane & 15;
    const int a_c = (lane >> 4) << 3;
    const int b_r = ((lane >> 4) << 3) | (lane & 7);
    const int b_c = ((lane >> 3) & 1) << 3;

    float acc[4][4] = {};

#pragma unroll
    for (int ks = 0; ks < 4; ks++) {
        uint32_t afh[4], afl[4];
        {
            uint32_t off = (uint32_t)((wy * 16 + a_r) * LDSB + ks * 16 + a_c) * 2u;
            ldsm4(afh, sAh + off);
            ldsm4(afl, sAl + off);
        }
        uint32_t bfh[2][4], bfl[2][4];
#pragma unroll
        for (int jn = 0; jn < 2; jn++) {
            uint32_t off = (uint32_t)((wx * 32 + jn * 16 + b_r) * LDSB + ks * 16 + b_c) * 2u;
            ldsm4(bfh[jn], sBh + off);
            ldsm4(bfl[jn], sBl + off);
        }
#pragma unroll
        for (int jn = 0; jn < 2; jn++)
#pragma unroll
            for (int hf = 0; hf < 2; hf++) {
                int j8 = jn * 2 + hf;
                mma16816(acc[j8], afh, &bfh[jn][hf * 2]);
                mma16816(acc[j8], afh, &bfl[jn][hf * 2]);
                mma16816(acc[j8], afl, &bfh[jn][hf * 2]);
            }
    }

    __nv_bfloat16* __restrict__ Ph = g_ph + (size_t)bh * SSQ;
    __nv_bfloat16* __restrict__ Pl = g_pl + (size_t)bh * SSQ;
    const int er = lane >> 2;
    const int ec = (lane & 3) * 2;
#pragma unroll
    for (int j8 = 0; j8 < 4; j8++) {
        int m = m0 + wy * 16 + er;
        int n = n0 + wx * 32 + j8 * 8 + ec;
#pragma unroll
        for (int half = 0; half < 2; half++) {
            float v0 = acc[j8][half * 2 + 0] * 0.125f;
            float v1 = acc[j8][half * 2 + 1] * 0.125f;
            __nv_bfloat16 h0, l0, h1, l1;
            split2(v0, h0, l0);
            split2(v1, h1, l1);
            size_t di = (size_t)(m + half * 8) * SS_ + n;
            *(__nv_bfloat162*)(Ph + di) = __halves2bfloat162(h0, h1);
            *(__nv_bfloat162*)(Pl + di) = __halves2bfloat162(l0, l1);
        }
    }
}

// ============================================================================
// fused softmax + head-mean (UNCHANGED, validated)
// ============================================================================
__global__ __launch_bounds__(256) void softmax_mean_kernel(float* __restrict__ attn_mean)
{
    const int bq = blockIdx.x;
    const int b = bq >> 11;
    const int q = bq & (SS_ - 1);
    const int tid = threadIdx.x;
    __shared__ float sm[8];

    float macc[8] = {};

    for (int h = 0; h < HH; h++) {
        const size_t row = ((size_t)(b * HH + h) * SS_ + q) * SS_;

        float v[8];
        float mx = -3.4e38f;
#pragma unroll
        for (int i = 0; i < 8; i++) {
            size_t idx = row + tid + i * 256;
            v[i] = __bfloat162float(g_ph[idx]) + __bfloat162float(g_pl[idx]);
            mx = fmaxf(mx, v[i]);
        }
#pragma unroll
        for (int o = 16; o; o >>= 1) mx = fmaxf(mx, __shfl_xor_sync(~0u, mx, o));
        if ((tid & 31) == 0) sm[tid >> 5] = mx;
        __syncthreads();
        mx = sm[0];
#pragma unroll
        for (int i = 1; i < 8; i++) mx = fmaxf(mx, sm[i]);
        __syncthreads();

        float sum = 0.f;
#pragma unroll
        for (int i = 0; i < 8; i++) { v[i] = __expf(v[i] - mx); sum += v[i]; }
#pragma unroll
        for (int o = 16; o; o >>= 1) sum += __shfl_xor_sync(~0u, sum, o);
        if ((tid & 31) == 0) sm[tid >> 5] = sum;
        __syncthreads();
        float total = 0.f;
#pragma unroll
        for (int i = 0; i < 8; i++) total += sm[i];
        __syncthreads();

        const float inv = 1.0f / total;
#pragma unroll
        for (int i = 0; i < 8; i++) {
            float pv = v[i] * inv;
            macc[i] += pv;
            __nv_bfloat16 hi, lo; split2(pv, hi, lo);
            size_t idx = row + tid + i * 256;
            g_ph[idx] = hi;
            g_pl[idx] = lo;
        }
    }

    const float inv16 = 1.0f / 16.0f;
    float* dst = attn_mean + (size_t)bq * SS_;
#pragma unroll
    for (int i = 0; i < 8; i++) dst[tid + i * 256] = macc[i] * inv16;
}

// ============================================================================
// ctx = P @ V via mma; epilogue bf16 hi/lo gathered [b, s, h*64+dh]
// ============================================================================
__global__ __launch_bounds__(256) void ctx_mma_kernel()
{
    __shared__ __align__(16) __nv_bfloat16 Ah[64][LDSB];
    __shared__ __align__(16) __nv_bfloat16 Al[64][LDSB];
    __shared__ __align__(16) __nv_bfloat16 Bh[64][LDSB];
    __shared__ __align__(16) __nv_bfloat16 Bl[64][LDSB];

    const int bh = blockIdx.y;
    const int m0 = blockIdx.x * 64;
    const int tid = threadIdx.x;
    const int wid = tid >> 5;
    const int lane = tid & 31;

    const __nv_bfloat16* Ph = g_ph + (size_t)bh * SSQ;
    const __nv_bfloat16* Pl = g_pl + (size_t)bh * SSQ;
    const __nv_bfloat16* Vh = g_vth + (size_t)bh * HD * SS_;
    const __nv_bfloat16* Vl = g_vtl + (size_t)bh * HD * SS_;

    const uint32_t sAh = smem_u32(&Ah[0][0]);
    const uint32_t sAl = smem_u32(&Al[0][0]);
    const uint32_t sBh = smem_u32(&Bh[0][0]);
    const uint32_t sBl = smem_u32(&Bl[0][0]);

    const int wy = wid >> 1;
    const int wx = wid & 1;
    const int a_r = lane & 15;
    const int a_c = (lane >> 4) << 3;
    const int b_r = ((lane >> 4) << 3) | (lane & 7);
    const int b_c = ((lane >> 3) & 1) << 3;

    float acc[4][4] = {};

    for (int it = 0; it < 32; ++it) {
        const int k0 = it * 64;
        for (int idx = tid; idx < 2048; idx += 256) {
            int c = idx & 7;
            int r = (idx >> 3) & 63;
            int sel = idx >> 9;
            const __nv_bfloat16* src;
            __nv_bfloat16* dst;
            if (sel == 0)      { src = Ph + (size_t)(m0 + r) * SS_ + k0; dst = &Ah[r][0]; }
            else if (sel == 1) { src = Pl + (size_t)(m0 + r) * SS_ + k0; dst = &Al[r][0]; }
            else if (sel == 2) { src = Vh + (size_t)r * SS_ + k0;        dst = &Bh[r][0]; }
            else               { src = Vl + (size_t)r * SS_ + k0;        dst = &Bl[r][0]; }
            uint4 val = ((const uint4*)src)[c];
            *(uint4*)(dst + c * 8) = val;
        }
        __syncthreads();

#pragma unroll
        for (int ks = 0; ks < 4; ks++) {
            uint32_t afh[4], afl[4];
            {
                uint32_t off = (uint32_t)((wy * 16 + a_r) * LDSB + ks * 16 + a_c) * 2u;
                ldsm4(afh, sAh + off);
                ldsm4(afl, sAl + off);
            }
            uint32_t bfh[2][4], bfl[2][4];
#pragma unroll
            for (int jn = 0; jn < 2; jn++) {
                uint32_t off = (uint32_t)((wx * 32 + jn * 16 + b_r) * LDSB + ks * 16 + b_c) * 2u;
                ldsm4(bfh[jn], sBh + off);
                ldsm4(bfl[jn], sBl + off);
            }
#pragma unroll
            for (int jn = 0; jn < 2; jn++)
#pragma unroll
                for (int hf = 0; hf < 2; hf++) {
                    int j8 = jn * 2 + hf;
                    mma16816(acc[j8], afh, &bfh[jn][hf * 2]);
                    mma16816(acc[j8], afh, &bfl[jn][hf * 2]);
                    mma16816(acc[j8], afl, &bfh[jn][hf * 2]);
                }
        }
        __syncthreads();
    }

    const int b = bh >> 4, h = bh & 15;
    const int er = lane >> 2;
    const int ec = (lane & 3) * 2;
#pragma unroll
    for (int j8 = 0; j8 < 4; j8++) {
#pragma unroll
        for (int half = 0; half < 2; half++) {
            int m = m0 + wy * 16 + er + half * 8;
            int n = wx * 32 + j8 * 8 + ec;        // dh
            float v0 = acc[j8][half * 2 + 0];
            float v1 = acc[j8][half * 2 + 1];
            __nv_bfloat16 h0, l0, h1, l1;
            split2(v0, h0, l0);
            split2(v1, h1, l1);
            size_t di = ((size_t)(b * SS_ + m)) * DD + h * HD + n;
            *(__nv_bfloat162*)(g_ch + di) = __halves2bfloat162(h0, h1);
            *(__nv_bfloat162*)(g_cl + di) = __halves2bfloat162(l0, l1);
        }
    }
}

// ============================================================================
extern "C" void kernel_launch(void* const* d_in, const int* in_sizes, int n_in,
                              void* d_out, int out_size)
{
    const float* x  = (const float*)d_in[0];
    const float* Wq = (const float*)d_in[1];
    const float* bq = (const float*)d_in[2];
    const float* Wk = (const float*)d_in[3];
    const float* bk = (const float*)d_in[4];
    const float* Wv = (const float*)d_in[5];
    const float* bv = (const float*)d_in[6];
    const float* Wo = (const float*)d_in[7];
    const float* bo = (const float*)d_in[8];

    float* out = (float*)d_out;                        // [B,S,D]
    float* attn_mean = out + (size_t)BB * SS_ * DD;    // [B,S,S]

    // prep
    split_x_kernel<<<(M_TOT * DD + 255) / 256, 256>>>(x);
    dim3 tw(32, 8), gw(DD / 32, DD / 32);
    transpose_split_w_kernel<<<gw, tw>>>(Wq, 0);
    transpose_split_w_kernel<<<gw, tw>>>(Wk, 1);
    transpose_split_w_kernel<<<gw, tw>>>(Wv, 2);
    transpose_split_w_kernel<<<gw, tw>>>(Wo, 3);

    // projections: M=4096, N=1024, K=1024
    dim3 gp(M_TOT / 64, DD / 64);        // (64,16)
    gemm_mma_kernel<<<gp, 256>>>(0, bq, nullptr);
    gemm_mma_kernel<<<gp, 256>>>(1, bk, nullptr);
    gemm_mma_kernel<<<gp, 256>>>(2, bv, nullptr);

    // scores
    dim3 gs(SS_ / 64, SS_ / 64, BH);     // (32,32,32)
    scores_mma_kernel<<<gs, 256>>>();

    // softmax + head mean
    softmax_mean_kernel<<<BB * SS_, 256>>>(attn_mean);

    // ctx
    dim3 gc(SS_ / 64, BH);               // (32,32)
    ctx_mma_kernel<<<gc, 256>>>();

    // out: M=4096, N=1024, K=1024
    gemm_mma_kernel<<<gp, 256>>>(3, bo, out);
}

// round 9
// speedup vs baseline: 2.1572x; 1.3006x over previous
#include <cuda_runtime.h>
#include <cuda_bf16.h>
#include <cstdint>

#define BB 2
#define SS_ 2048
#define DD 1024
#define HH 16
#define HD 64
#define M_TOT (BB * SS_)        // 4096
#define BH (BB * HH)            // 32
#define SSQ ((size_t)SS_ * SS_) // 4194304 per (b,h)

#define LDSB 72                 // bf16 per smem row (144B, 16B multiple)
#define STAGE_ELEMS (4 * 64 * LDSB)
#define STAGE_BYTES (STAGE_ELEMS * 2)          // 36864
#define PIPE_SMEM   (2 * STAGE_BYTES)          // 73728

// -------- scratch (~630 MB, proven range) --------
__device__ __align__(256) __nv_bfloat16 g_xh[(size_t)M_TOT * DD];
__device__ __align__(256) __nv_bfloat16 g_xl[(size_t)M_TOT * DD];
__device__ __align__(256) __nv_bfloat16 g_wth[(size_t)4 * DD * DD];   // W^T hi (q,k,v,o)
__device__ __align__(256) __nv_bfloat16 g_wtl[(size_t)4 * DD * DD];
__device__ __align__(256) __nv_bfloat16 g_qh[(size_t)BH * SS_ * HD];  // pre-scaled by 1/8
__device__ __align__(256) __nv_bfloat16 g_ql[(size_t)BH * SS_ * HD];
__device__ __align__(256) __nv_bfloat16 g_kh[(size_t)BH * SS_ * HD];
__device__ __align__(256) __nv_bfloat16 g_kl[(size_t)BH * SS_ * HD];
__device__ __align__(256) __nv_bfloat16 g_vth[(size_t)BH * HD * SS_]; // V^T [bh,dh,s]
__device__ __align__(256) __nv_bfloat16 g_vtl[(size_t)BH * HD * SS_];
__device__ __align__(256) __nv_bfloat16 g_ph[(size_t)BH * SSQ];
__device__ __align__(256) __nv_bfloat16 g_pl[(size_t)BH * SSQ];
__device__ __align__(256) __nv_bfloat16 g_ch[(size_t)M_TOT * DD];     // ctx [b,s,h*64+dh]
__device__ __align__(256) __nv_bfloat16 g_cl[(size_t)M_TOT * DD];

// ======================= small helpers ======================================
__device__ __forceinline__ void split2(float v, __nv_bfloat16& hi, __nv_bfloat16& lo) {
    hi = __float2bfloat16(v);
    lo = __float2bfloat16(v - __bfloat162float(hi));
}

__device__ __forceinline__ uint32_t smem_u32(const void* p) {
    uint32_t a;
    asm("{ .reg .u64 t; cvta.to.shared.u64 t, %1; cvt.u32.u64 %0, t; }" : "=r"(a) : "l"(p));
    return a;
}

__device__ __forceinline__ void ldsm4(uint32_t* r, uint32_t addr) {
    asm volatile("ldmatrix.sync.aligned.m8n8.x4.shared.b16 {%0,%1,%2,%3}, [%4];"
                 : "=r"(r[0]), "=r"(r[1]), "=r"(r[2]), "=r"(r[3]) : "r"(addr));
}

__device__ __forceinline__ void mma16816(float* d, const uint32_t* a, const uint32_t* b) {
    asm volatile(
        "mma.sync.aligned.m16n8k16.row.col.f32.bf16.bf16.f32 "
        "{%0,%1,%2,%3}, {%4,%5,%6,%7}, {%8,%9}, {%0,%1,%2,%3};"
        : "+f"(d[0]), "+f"(d[1]), "+f"(d[2]), "+f"(d[3])
        : "r"(a[0]), "r"(a[1]), "r"(a[2]), "r"(a[3]), "r"(b[0]), "r"(b[1]));
}

__device__ __forceinline__ void cp_async16(uint32_t saddr, const void* gptr) {
    asm volatile("cp.async.cg.shared.global [%0], [%1], 16;" :: "r"(saddr), "l"(gptr));
}
__device__ __forceinline__ void cp_async_commit() {
    asm volatile("cp.async.commit_group;" ::: "memory");
}
__device__ __forceinline__ void cp_async_wait0() {
    asm volatile("cp.async.wait_group 0;" ::: "memory");
}

// ======================= prep kernels =======================================
__global__ __launch_bounds__(256) void split_x_kernel(const float* __restrict__ x)
{
    size_t i = (size_t)blockIdx.x * 256 + threadIdx.x;
    if (i < (size_t)M_TOT * DD) {
        __nv_bfloat16 h, l;
        split2(x[i], h, l);
        g_xh[i] = h; g_xl[i] = l;
    }
}

__global__ __launch_bounds__(256) void transpose_split_w_kernel(
    const float* __restrict__ W, int which)
{
    __shared__ __align__(16) float t[32][33];
    const int tx = threadIdx.x, ty = threadIdx.y;   // (32,8)
    const int n0 = blockIdx.x * 32, k0 = blockIdx.y * 32;
    __nv_bfloat16* __restrict__ th = g_wth + (size_t)which * DD * DD;
    __nv_bfloat16* __restrict__ tl = g_wtl + (size_t)which * DD * DD;

#pragma unroll
    for (int j = 0; j < 4; j++)
        t[ty + 8 * j][tx] = W[(size_t)(k0 + ty + 8 * j) * DD + n0 + tx];
    __syncthreads();
#pragma unroll
    for (int j = 0; j < 4; j++) {
        float v = t[tx][ty + 8 * j];
        __nv_bfloat16 hi, lo; split2(v, hi, lo);
        size_t di = (size_t)(n0 + ty + 8 * j) * DD + k0 + tx;
        th[di] = hi; tl[di] = lo;
    }
}

// ============================================================================
// Generic 64x64-tile split-bf16 mma GEMM, 2-stage cp.async pipeline.
// mode: 0 q=(x@Wq^T+bq)/8 -> g_qh/g_ql ; 1 k -> g_kh/g_kl ; 2 v -> V^T ;
//       3 out = ctx@Wo^T + bo -> fout (fp32)
// ============================================================================
__global__ __launch_bounds__(256) void gemm_mma_kernel(
    int mode, const float* __restrict__ bias, float* __restrict__ fout)
{
    extern __shared__ __align__(16) __nv_bfloat16 dynsm[];

    const __nv_bfloat16* Ah = (mode == 3) ? g_ch : g_xh;
    const __nv_bfloat16* Al = (mode == 3) ? g_cl : g_xl;
    const __nv_bfloat16* Bh = g_wth + (size_t)mode * DD * DD;
    const __nv_bfloat16* Bl = g_wtl + (size_t)mode * DD * DD;
    const int K = DD;

    const int m0 = blockIdx.x * 64;
    const int n0 = blockIdx.y * 64;
    const int tid = threadIdx.x;
    const int wid = tid >> 5;
    const int lane = tid & 31;
    const uint32_t sbase = smem_u32(dynsm);

    const int wy = wid >> 1;
    const int wx = wid & 1;
    const int a_r = lane & 15;
    const int a_c = (lane >> 4) << 3;
    const int b_r = ((lane >> 4) << 3) | (lane & 7);
    const int b_c = ((lane >> 3) & 1) << 3;

    float acc[4][4] = {};

    const int niter = K >> 6;

    // fill(it, stage): 2048 16B chunks via cp.async
    auto fill = [&](int it, int stage) {
        const int k0 = it << 6;
        const uint32_t stb = sbase + stage * STAGE_BYTES;
        for (int idx = tid; idx < 2048; idx += 256) {
            int c = idx & 7;
            int r = (idx >> 3) & 63;
            int sel = idx >> 9;
            const __nv_bfloat16* src;
            if (sel == 0)      src = Ah + (size_t)(m0 + r) * K + k0;
            else if (sel == 1) src = Al + (size_t)(m0 + r) * K + k0;
            else if (sel == 2) src = Bh + (size_t)(n0 + r) * K + k0;
            else               src = Bl + (size_t)(n0 + r) * K + k0;
            uint32_t daddr = stb + (uint32_t)(sel * 64 * LDSB + r * LDSB + c * 8) * 2u;
            cp_async16(daddr, src + c * 8);
        }
    };

    fill(0, 0);
    cp_async_commit();
    int stage = 0;

    for (int it = 0; it < niter; ++it) {
        cp_async_wait0();
        __syncthreads();
        if (it + 1 < niter) { fill(it + 1, stage ^ 1); cp_async_commit(); }

        const uint32_t stb = sbase + stage * STAGE_BYTES;
        const uint32_t sAh = stb;
        const uint32_t sAl = stb + (uint32_t)(64 * LDSB) * 2u;
        const uint32_t sBh = stb + (uint32_t)(2 * 64 * LDSB) * 2u;
        const uint32_t sBl = stb + (uint32_t)(3 * 64 * LDSB) * 2u;

#pragma unroll
        for (int ks = 0; ks < 4; ks++) {
            uint32_t afh[4], afl[4];
            {
                uint32_t off = (uint32_t)((wy * 16 + a_r) * LDSB + ks * 16 + a_c) * 2u;
                ldsm4(afh, sAh + off);
                ldsm4(afl, sAl + off);
            }
            uint32_t bfh[2][4], bfl[2][4];
#pragma unroll
            for (int jn = 0; jn < 2; jn++) {
                uint32_t off = (uint32_t)((wx * 32 + jn * 16 + b_r) * LDSB + ks * 16 + b_c) * 2u;
                ldsm4(bfh[jn], sBh + off);
                ldsm4(bfl[jn], sBl + off);
            }
#pragma unroll
            for (int jn = 0; jn < 2; jn++)
#pragma unroll
                for (int hf = 0; hf < 2; hf++) {
                    int j8 = jn * 2 + hf;
                    mma16816(acc[j8], afh, &bfh[jn][hf * 2]);
                    mma16816(acc[j8], afh, &bfl[jn][hf * 2]);
                    mma16816(acc[j8], afl, &bfh[jn][hf * 2]);
                }
        }
        __syncthreads();
        stage ^= 1;
    }

    // ---------------- epilogue --------------------------------------------
    const int er = lane >> 2;
    const int ec = (lane & 3) * 2;
#pragma unroll
    for (int j8 = 0; j8 < 4; j8++) {
#pragma unroll
        for (int half = 0; half < 2; half++) {
            int m = m0 + wy * 16 + er + half * 8;
            int n = n0 + wx * 32 + j8 * 8 + ec;
            float v0 = acc[j8][half * 2 + 0];
            float v1 = acc[j8][half * 2 + 1];
            if (mode == 3) {
                float2 o = make_float2(v0 + bias[n], v1 + bias[n + 1]);
                *(float2*)(fout + (size_t)m * DD + n) = o;
            } else {
                int b = m >> 11, s = m & (SS_ - 1);
                int h = n >> 6, dh = n & 63;
                float b0 = v0 + bias[n], b1 = v1 + bias[n + 1];
                if (mode == 0) { b0 *= 0.125f; b1 *= 0.125f; }   // fold score scale into q
                __nv_bfloat16 h0, l0, h1, l1;
                split2(b0, h0, l0);
                split2(b1, h1, l1);
                if (mode == 0) {
                    size_t di = (((size_t)(b * HH + h)) * SS_ + s) * HD + dh;
                    *(__nv_bfloat162*)(g_qh + di) = __halves2bfloat162(h0, h1);
                    *(__nv_bfloat162*)(g_ql + di) = __halves2bfloat162(l0, l1);
                } else if (mode == 1) {
                    size_t di = (((size_t)(b * HH + h)) * SS_ + s) * HD + dh;
                    *(__nv_bfloat162*)(g_kh + di) = __halves2bfloat162(h0, h1);
                    *(__nv_bfloat162*)(g_kl + di) = __halves2bfloat162(l0, l1);
                } else {   // mode == 2 : V^T [bh,dh,s]
                    size_t di = (((size_t)(b * HH + h)) * HD + dh) * SS_ + s;
                    g_vth[di] = h0; g_vtl[di] = l0;
                    g_vth[di + SS_] = h1; g_vtl[di + SS_] = l1;
                }
            }
        }
    }
}

// ============================================================================
// scores via mma (validated; q pre-scaled so no 0.125 here)
// ============================================================================
__global__ __launch_bounds__(256) void scores_mma_kernel()
{
    __shared__ __align__(16) __nv_bfloat16 Ah[64][LDSB];
    __shared__ __align__(16) __nv_bfloat16 Al[64][LDSB];
    __shared__ __align__(16) __nv_bfloat16 Bh[64][LDSB];
    __shared__ __align__(16) __nv_bfloat16 Bl[64][LDSB];

    const int bh = blockIdx.z;
    const int m0 = blockIdx.x * 64;
    const int n0 = blockIdx.y * 64;
    const int tid = threadIdx.x;
    const int wid = tid >> 5;
    const int lane = tid & 31;

    const __nv_bfloat16* Qh = g_qh + (size_t)bh * SS_ * HD;
    const __nv_bfloat16* Ql = g_ql + (size_t)bh * SS_ * HD;
    const __nv_bfloat16* Kh = g_kh + (size_t)bh * SS_ * HD;
    const __nv_bfloat16* Kl = g_kl + (size_t)bh * SS_ * HD;

    for (int idx = tid; idx < 2048; idx += 256) {
        int c = idx & 7;
        int r = (idx >> 3) & 63;
        int sel = idx >> 9;
        const __nv_bfloat16* src;
        __nv_bfloat16* dst;
        if (sel == 0)      { src = Qh + (size_t)(m0 + r) * HD; dst = &Ah[r][0]; }
        else if (sel == 1) { src = Ql + (size_t)(m0 + r) * HD; dst = &Al[r][0]; }
        else if (sel == 2) { src = Kh + (size_t)(n0 + r) * HD; dst = &Bh[r][0]; }
        else               { src = Kl + (size_t)(n0 + r) * HD; dst = &Bl[r][0]; }
        uint4 val = ((const uint4*)src)[c];
        *(uint4*)(dst + c * 8) = val;
    }
    __syncthreads();

    const uint32_t sAh = smem_u32(&Ah[0][0]);
    const uint32_t sAl = smem_u32(&Al[0][0]);
    const uint32_t sBh = smem_u32(&Bh[0][0]);
    const uint32_t sBl = smem_u32(&Bl[0][0]);

    const int wy = wid >> 1;
    const int wx = wid & 1;
    const int a_r = lane & 15;
    const int a_c = (lane >> 4) << 3;
    const int b_r = ((lane >> 4) << 3) | (lane & 7);
    const int b_c = ((lane >> 3) & 1) << 3;

    float acc[4][4] = {};

#pragma unroll
    for (int ks = 0; ks < 4; ks++) {
        uint32_t afh[4], afl[4];
        {
            uint32_t off = (uint32_t)((wy * 16 + a_r) * LDSB + ks * 16 + a_c) * 2u;
            ldsm4(afh, sAh + off);
            ldsm4(afl, sAl + off);
        }
        uint32_t bfh[2][4], bfl[2][4];
#pragma unroll
        for (int jn = 0; jn < 2; jn++) {
            uint32_t off = (uint32_t)((wx * 32 + jn * 16 + b_r) * LDSB + ks * 16 + b_c) * 2u;
            ldsm4(bfh[jn], sBh + off);
            ldsm4(bfl[jn], sBl + off);
        }
#pragma unroll
        for (int jn = 0; jn < 2; jn++)
#pragma unroll
            for (int hf = 0; hf < 2; hf++) {
                int j8 = jn * 2 + hf;
                mma16816(acc[j8], afh, &bfh[jn][hf * 2]);
                mma16816(acc[j8], afh, &bfl[jn][hf * 2]);
                mma16816(acc[j8], afl, &bfh[jn][hf * 2]);
            }
    }

    __nv_bfloat16* __restrict__ Ph = g_ph + (size_t)bh * SSQ;
    __nv_bfloat16* __restrict__ Pl = g_pl + (size_t)bh * SSQ;
    const int er = lane >> 2;
    const int ec = (lane & 3) * 2;
#pragma unroll
    for (int j8 = 0; j8 < 4; j8++) {
        int m = m0 + wy * 16 + er;
        int n = n0 + wx * 32 + j8 * 8 + ec;
#pragma unroll
        for (int half = 0; half < 2; half++) {
            float v0 = acc[j8][half * 2 + 0];
            float v1 = acc[j8][half * 2 + 1];
            __nv_bfloat16 h0, l0, h1, l1;
            split2(v0, h0, l0);
            split2(v1, h1, l1);
            size_t di = (size_t)(m + half * 8) * SS_ + n;
            *(__nv_bfloat162*)(Ph + di) = __halves2bfloat162(h0, h1);
            *(__nv_bfloat162*)(Pl + di) = __halves2bfloat162(l0, l1);
        }
    }
}

// ============================================================================
// fused softmax + head-mean, fully vectorized (uint4 per stream per thread).
// Thread t handles 8 contiguous cols t*8..t*8+7.
// ============================================================================
__global__ __launch_bounds__(256) void softmax_mean_kernel(float* __restrict__ attn_mean)
{
    const int bq = blockIdx.x;
    const int b = bq >> 11;
    const int q = bq & (SS_ - 1);
    const int tid = threadIdx.x;
    const int col0 = tid * 8;
    __shared__ float sm[8];

    float macc[8] = {};

    for (int h = 0; h < HH; h++) {
        const size_t row = ((size_t)(b * HH + h) * SS_ + q) * SS_;

        uint4 hv = *(const uint4*)(g_ph + row + col0);
        uint4 lv = *(const uint4*)(g_pl + row + col0);
        const __nv_bfloat162* hp = (const __nv_bfloat162*)&hv;
        const __nv_bfloat162* lp = (const __nv_bfloat162*)&lv;

        float v[8];
        float mx = -3.4e38f;
#pragma unroll
        for (int j = 0; j < 4; j++) {
            float2 a = __bfloat1622float2(hp[j]);
            float2 l2 = __bfloat1622float2(lp[j]);
            v[2 * j] = a.x + l2.x;
            v[2 * j + 1] = a.y + l2.y;
            mx = fmaxf(mx, fmaxf(v[2 * j], v[2 * j + 1]));
        }
#pragma unroll
        for (int o = 16; o; o >>= 1) mx = fmaxf(mx, __shfl_xor_sync(~0u, mx, o));
        if ((tid & 31) == 0) sm[tid >> 5] = mx;
        __syncthreads();
        mx = sm[0];
#pragma unroll
        for (int i = 1; i < 8; i++) mx = fmaxf(mx, sm[i]);
        __syncthreads();

        float sum = 0.f;
#pragma unroll
        for (int i = 0; i < 8; i++) { v[i] = __expf(v[i] - mx); sum += v[i]; }
#pragma unroll
        for (int o = 16; o; o >>= 1) sum += __shfl_xor_sync(~0u, sum, o);
        if ((tid & 31) == 0) sm[tid >> 5] = sum;
        __syncthreads();
        float total = 0.f;
#pragma unroll
        for (int i = 0; i < 8; i++) total += sm[i];
        __syncthreads();

        const float inv = 1.0f / total;
        uint4 ho, lo4;
        __nv_bfloat162* hop = (__nv_bfloat162*)&ho;
        __nv_bfloat162* lop = (__nv_bfloat162*)&lo4;
#pragma unroll
        for (int j = 0; j < 4; j++) {
            float p0 = v[2 * j] * inv;
            float p1 = v[2 * j + 1] * inv;
            macc[2 * j] += p0;
            macc[2 * j + 1] += p1;
            __nv_bfloat16 h0, l0, h1, l1;
            split2(p0, h0, l0);
            split2(p1, h1, l1);
            hop[j] = __halves2bfloat162(h0, h1);
            lop[j] = __halves2bfloat162(l0, l1);
        }
        *(uint4*)(g_ph + row + col0) = ho;
        *(uint4*)(g_pl + row + col0) = lo4;
    }

    const float inv16 = 1.0f / 16.0f;
    float* dst = attn_mean + (size_t)bq * SS_ + col0;
    float4 o0 = make_float4(macc[0] * inv16, macc[1] * inv16, macc[2] * inv16, macc[3] * inv16);
    float4 o1 = make_float4(macc[4] * inv16, macc[5] * inv16, macc[6] * inv16, macc[7] * inv16);
    *(float4*)(dst) = o0;
    *(float4*)(dst + 4) = o1;
}

// ============================================================================
// ctx = P @ V via mma, 2-stage cp.async pipeline; epilogue bf16 hi/lo
// gathered [b, s, h*64+dh]
// ============================================================================
__global__ __launch_bounds__(256) void ctx_mma_kernel()
{
    extern __shared__ __align__(16) __nv_bfloat16 dynsm[];

    const int bh = blockIdx.y;
    const int m0 = blockIdx.x * 64;
    const int tid = threadIdx.x;
    const int wid = tid >> 5;
    const int lane = tid & 31;

    const __nv_bfloat16* Ph = g_ph + (size_t)bh * SSQ;
    const __nv_bfloat16* Pl = g_pl + (size_t)bh * SSQ;
    const __nv_bfloat16* Vh = g_vth + (size_t)bh * HD * SS_;
    const __nv_bfloat16* Vl = g_vtl + (size_t)bh * HD * SS_;

    const uint32_t sbase = smem_u32(dynsm);

    const int wy = wid >> 1;
    const int wx = wid & 1;
    const int a_r = lane & 15;
    const int a_c = (lane >> 4) << 3;
    const int b_r = ((lane >> 4) << 3) | (lane & 7);
    const int b_c = ((lane >> 3) & 1) << 3;

    float acc[4][4] = {};

    auto fill = [&](int it, int stage) {
        const int k0 = it * 64;
        const uint32_t stb = sbase + stage * STAGE_BYTES;
        for (int idx = tid; idx < 2048; idx += 256) {
            int c = idx & 7;
            int r = (idx >> 3) & 63;
            int sel = idx >> 9;
            const __nv_bfloat16* src;
            if (sel == 0)      src = Ph + (size_t)(m0 + r) * SS_ + k0;
            else if (sel == 1) src = Pl + (size_t)(m0 + r) * SS_ + k0;
            else if (sel == 2) src = Vh + (size_t)r * SS_ + k0;
            else               src = Vl + (size_t)r * SS_ + k0;
            uint32_t daddr = stb + (uint32_t)(sel * 64 * LDSB + r * LDSB + c * 8) * 2u;
            cp_async16(daddr, src + c * 8);
        }
    };

    fill(0, 0);
    cp_async_commit();
    int stage = 0;

    for (int it = 0; it < 32; ++it) {
        cp_async_wait0();
        __syncthreads();
        if (it + 1 < 32) { fill(it + 1, stage ^ 1); cp_async_commit(); }

        const uint32_t stb = sbase + stage * STAGE_BYTES;
        const uint32_t sAh = stb;
        const uint32_t sAl = stb + (uint32_t)(64 * LDSB) * 2u;
        const uint32_t sBh = stb + (uint32_t)(2 * 64 * LDSB) * 2u;
        const uint32_t sBl = stb + (uint32_t)(3 * 64 * LDSB) * 2u;

#pragma unroll
        for (int ks = 0; ks < 4; ks++) {
            uint32_t afh[4], afl[4];
            {
                uint32_t off = (uint32_t)((wy * 16 + a_r) * LDSB + ks * 16 + a_c) * 2u;
                ldsm4(afh, sAh + off);
                ldsm4(afl, sAl + off);
            }
            uint32_t bfh[2][4], bfl[2][4];
#pragma unroll
            for (int jn = 0; jn < 2; jn++) {
                uint32_t off = (uint32_t)((wx * 32 + jn * 16 + b_r) * LDSB + ks * 16 + b_c) * 2u;
                ldsm4(bfh[jn], sBh + off);
                ldsm4(bfl[jn], sBl + off);
            }
#pragma unroll
            for (int jn = 0; jn < 2; jn++)
#pragma unroll
                for (int hf = 0; hf < 2; hf++) {
                    int j8 = jn * 2 + hf;
                    mma16816(acc[j8], afh, &bfh[jn][hf * 2]);
                    mma16816(acc[j8], afh, &bfl[jn][hf * 2]);
                    mma16816(acc[j8], afl, &bfh[jn][hf * 2]);
                }
        }
        __syncthreads();
        stage ^= 1;
    }

    const int b = bh >> 4, h = bh & 15;
    const int er = lane >> 2;
    const int ec = (lane & 3) * 2;
#pragma unroll
    for (int j8 = 0; j8 < 4; j8++) {
#pragma unroll
        for (int half = 0; half < 2; half++) {
            int m = m0 + wy * 16 + er + half * 8;
            int n = wx * 32 + j8 * 8 + ec;        // dh
            float v0 = acc[j8][half * 2 + 0];
            float v1 = acc[j8][half * 2 + 1];
            __nv_bfloat16 h0, l0, h1, l1;
            split2(v0, h0, l0);
            split2(v1, h1, l1);
            size_t di = ((size_t)(b * SS_ + m)) * DD + h * HD + n;
            *(__nv_bfloat162*)(g_ch + di) = __halves2bfloat162(h0, h1);
            *(__nv_bfloat162*)(g_cl + di) = __halves2bfloat162(l0, l1);
        }
    }
}

// ============================================================================
extern "C" void kernel_launch(void* const* d_in, const int* in_sizes, int n_in,
                              void* d_out, int out_size)
{
    const float* x  = (const float*)d_in[0];
    const float* Wq = (const float*)d_in[1];
    const float* bq = (const float*)d_in[2];
    const float* Wk = (const float*)d_in[3];
    const float* bk = (const float*)d_in[4];
    const float* Wv = (const float*)d_in[5];
    const float* bv = (const float*)d_in[6];
    const float* Wo = (const float*)d_in[7];
    const float* bo = (const float*)d_in[8];

    float* out = (float*)d_out;                        // [B,S,D]
    float* attn_mean = out + (size_t)BB * SS_ * DD;    // [B,S,S]

    cudaFuncSetAttribute(gemm_mma_kernel, cudaFuncAttributeMaxDynamicSharedMemorySize, PIPE_SMEM);
    cudaFuncSetAttribute(ctx_mma_kernel,  cudaFuncAttributeMaxDynamicSharedMemorySize, PIPE_SMEM);

    // prep
    split_x_kernel<<<(M_TOT * DD + 255) / 256, 256>>>(x);
    dim3 tw(32, 8), gw(DD / 32, DD / 32);
    transpose_split_w_kernel<<<gw, tw>>>(Wq, 0);
    transpose_split_w_kernel<<<gw, tw>>>(Wk, 1);
    transpose_split_w_kernel<<<gw, tw>>>(Wv, 2);
    transpose_split_w_kernel<<<gw, tw>>>(Wo, 3);

    // projections: M=4096, N=1024, K=1024
    dim3 gp(M_TOT / 64, DD / 64);        // (64,16)
    gemm_mma_kernel<<<gp, 256, PIPE_SMEM>>>(0, bq, nullptr);
    gemm_mma_kernel<<<gp, 256, PIPE_SMEM>>>(1, bk, nullptr);
    gemm_mma_kernel<<<gp, 256, PIPE_SMEM>>>(2, bv, nullptr);

    // scores
    dim3 gs(SS_ / 64, SS_ / 64, BH);     // (32,32,32)
    scores_mma_kernel<<<gs, 256>>>();

    // softmax + head mean
    softmax_mean_kernel<<<BB * SS_, 256>>>(attn_mean);

    // ctx
    dim3 gc(SS_ / 64, BH);               // (32,32)
    ctx_mma_kernel<<<gc, 256, PIPE_SMEM>>>();

    // out: M=4096, N=1024, K=1024
    gemm_mma_kernel<<<gp, 256, PIPE_SMEM>>>(3, bo, out);
}

// round 10
// speedup vs baseline: 2.1900x; 1.0152x over previous
#include <cuda_runtime.h>
#include <cuda_bf16.h>
#include <cstdint>

#define BB 2
#define SS_ 2048
#define DD 1024
#define HH 16
#define HD 64
#define M_TOT (BB * SS_)        // 4096
#define BH (BB * HH)            // 32
#define SSQ ((size_t)SS_ * SS_) // 4194304 per (b,h)

#define LDSB 72                 // bf16 per smem row (144B, 16B multiple)
// gemm/scores stage: 4 arrays x 128 rows
#define G_STAGE_BYTES (4 * 128 * LDSB * 2)     // 73728
#define G_PIPE_SMEM   (2 * G_STAGE_BYTES)      // 147456
// ctx stage: 4 arrays x 64 rows
#define C_STAGE_BYTES (4 * 64 * LDSB * 2)      // 36864
#define C_PIPE_SMEM   (2 * C_STAGE_BYTES)      // 73728

// -------- scratch (~630 MB, proven range) --------
__device__ __align__(256) __nv_bfloat16 g_xh[(size_t)M_TOT * DD];
__device__ __align__(256) __nv_bfloat16 g_xl[(size_t)M_TOT * DD];
__device__ __align__(256) __nv_bfloat16 g_wth[(size_t)4 * DD * DD];   // W^T hi (q,k,v,o)
__device__ __align__(256) __nv_bfloat16 g_wtl[(size_t)4 * DD * DD];
__device__ __align__(256) __nv_bfloat16 g_qh[(size_t)BH * SS_ * HD];  // pre-scaled by 1/8
__device__ __align__(256) __nv_bfloat16 g_ql[(size_t)BH * SS_ * HD];
__device__ __align__(256) __nv_bfloat16 g_kh[(size_t)BH * SS_ * HD];
__device__ __align__(256) __nv_bfloat16 g_kl[(size_t)BH * SS_ * HD];
__device__ __align__(256) __nv_bfloat16 g_vth[(size_t)BH * HD * SS_]; // V^T [bh,dh,s]
__device__ __align__(256) __nv_bfloat16 g_vtl[(size_t)BH * HD * SS_];
__device__ __align__(256) __nv_bfloat16 g_ph[(size_t)BH * SSQ];
__device__ __align__(256) __nv_bfloat16 g_pl[(size_t)BH * SSQ];
__device__ __align__(256) __nv_bfloat16 g_ch[(size_t)M_TOT * DD];     // ctx [b,s,h*64+dh]
__device__ __align__(256) __nv_bfloat16 g_cl[(size_t)M_TOT * DD];

// ======================= small helpers ======================================
__device__ __forceinline__ void split2(float v, __nv_bfloat16& hi, __nv_bfloat16& lo) {
    hi = __float2bfloat16(v);
    lo = __float2bfloat16(v - __bfloat162float(hi));
}

__device__ __forceinline__ uint32_t smem_u32(const void* p) {
    uint32_t a;
    asm("{ .reg .u64 t; cvta.to.shared.u64 t, %1; cvt.u32.u64 %0, t; }" : "=r"(a) : "l"(p));
    return a;
}

__device__ __forceinline__ void ldsm4(uint32_t* r, uint32_t addr) {
    asm volatile("ldmatrix.sync.aligned.m8n8.x4.shared.b16 {%0,%1,%2,%3}, [%4];"
                 : "=r"(r[0]), "=r"(r[1]), "=r"(r[2]), "=r"(r[3]) : "r"(addr));
}

__device__ __forceinline__ void mma16816(float* d, const uint32_t* a, const uint32_t* b) {
    asm volatile(
        "mma.sync.aligned.m16n8k16.row.col.f32.bf16.bf16.f32 "
        "{%0,%1,%2,%3}, {%4,%5,%6,%7}, {%8,%9}, {%0,%1,%2,%3};"
        : "+f"(d[0]), "+f"(d[1]), "+f"(d[2]), "+f"(d[3])
        : "r"(a[0]), "r"(a[1]), "r"(a[2]), "r"(a[3]), "r"(b[0]), "r"(b[1]));
}

__device__ __forceinline__ void cp_async16(uint32_t saddr, const void* gptr) {
    asm volatile("cp.async.cg.shared.global [%0], [%1], 16;" :: "r"(saddr), "l"(gptr));
}
__device__ __forceinline__ void cp_async_commit() {
    asm volatile("cp.async.commit_group;" ::: "memory");
}
__device__ __forceinline__ void cp_async_wait0() {
    asm volatile("cp.async.wait_group 0;" ::: "memory");
}

// ======================= prep kernels =======================================
__global__ __launch_bounds__(256) void split_x_kernel(const float* __restrict__ x)
{
    size_t i = (size_t)blockIdx.x * 256 + threadIdx.x;
    if (i < (size_t)M_TOT * DD) {
        __nv_bfloat16 h, l;
        split2(x[i], h, l);
        g_xh[i] = h; g_xl[i] = l;
    }
}

__global__ __launch_bounds__(256) void transpose_split_w_kernel(
    const float* __restrict__ W, int which)
{
    __shared__ __align__(16) float t[32][33];
    const int tx = threadIdx.x, ty = threadIdx.y;   // (32,8)
    const int n0 = blockIdx.x * 32, k0 = blockIdx.y * 32;
    __nv_bfloat16* __restrict__ th = g_wth + (size_t)which * DD * DD;
    __nv_bfloat16* __restrict__ tl = g_wtl + (size_t)which * DD * DD;

#pragma unroll
    for (int j = 0; j < 4; j++)
        t[ty + 8 * j][tx] = W[(size_t)(k0 + ty + 8 * j) * DD + n0 + tx];
    __syncthreads();
#pragma unroll
    for (int j = 0; j < 4; j++) {
        float v = t[tx][ty + 8 * j];
        __nv_bfloat16 hi, lo; split2(v, hi, lo);
        size_t di = (size_t)(n0 + ty + 8 * j) * DD + k0 + tx;
        th[di] = hi; tl[di] = lo;
    }
}

// ============================================================================
// 128x128-tile split-bf16 mma GEMM, BK=64, 2-stage cp.async pipeline.
// 8 warps: warp tile 32(m) x 64(n)   (wy = wid>>1, wx = wid&1)
// mode: 0 q=(x@Wq^T+bq)/8 ; 1 k ; 2 v -> V^T ; 3 out = ctx@Wo^T + bo -> fout
// grid (M/128, N/128)
// ============================================================================
__global__ __launch_bounds__(256) void gemm_mma_kernel(
    int mode, const float* __restrict__ bias, float* __restrict__ fout)
{
    extern __shared__ __align__(16) __nv_bfloat16 dynsm[];

    const __nv_bfloat16* Ah = (mode == 3) ? g_ch : g_xh;
    const __nv_bfloat16* Al = (mode == 3) ? g_cl : g_xl;
    const __nv_bfloat16* Bh = g_wth + (size_t)mode * DD * DD;
    const __nv_bfloat16* Bl = g_wtl + (size_t)mode * DD * DD;
    const int K = DD;

    const int m0 = blockIdx.x * 128;
    const int n0 = blockIdx.y * 128;
    const int tid = threadIdx.x;
    const int wid = tid >> 5;
    const int lane = tid & 31;
    const uint32_t sbase = smem_u32(dynsm);

    const int wy = wid >> 1;          // 0..3 -> m rows wy*32
    const int wx = wid & 1;           // 0..1 -> n cols wx*64
    const int a_r = lane & 15;
    const int a_c = (lane >> 4) << 3;
    const int b_r = ((lane >> 4) << 3) | (lane & 7);
    const int b_c = ((lane >> 3) & 1) << 3;

    float acc[2][8][4] = {};          // [mfrag][j8][4]

    const int niter = K >> 6;

    auto fill = [&](int it, int stage) {
        const int k0 = it << 6;
        const uint32_t stb = sbase + stage * G_STAGE_BYTES;
        for (int idx = tid; idx < 4096; idx += 256) {
            int c = idx & 7;
            int r = (idx >> 3) & 127;
            int sel = idx >> 10;
            const __nv_bfloat16* src;
            if (sel == 0)      src = Ah + (size_t)(m0 + r) * K + k0;
            else if (sel == 1) src = Al + (size_t)(m0 + r) * K + k0;
            else if (sel == 2) src = Bh + (size_t)(n0 + r) * K + k0;
            else               src = Bl + (size_t)(n0 + r) * K + k0;
            uint32_t daddr = stb + (uint32_t)(sel * 128 * LDSB + r * LDSB + c * 8) * 2u;
            cp_async16(daddr, src + c * 8);
        }
    };

    fill(0, 0);
    cp_async_commit();
    int stage = 0;

    for (int it = 0; it < niter; ++it) {
        cp_async_wait0();
        __syncthreads();
        if (it + 1 < niter) { fill(it + 1, stage ^ 1); cp_async_commit(); }

        const uint32_t stb = sbase + stage * G_STAGE_BYTES;
        const uint32_t sAh = stb;
        const uint32_t sAl = stb + (uint32_t)(128 * LDSB) * 2u;
        const uint32_t sBh = stb + (uint32_t)(2 * 128 * LDSB) * 2u;
        const uint32_t sBl = stb + (uint32_t)(3 * 128 * LDSB) * 2u;

#pragma unroll
        for (int ks = 0; ks < 4; ks++) {
            uint32_t afh[2][4], afl[2][4];
#pragma unroll
            for (int i = 0; i < 2; i++) {
                uint32_t off = (uint32_t)((wy * 32 + i * 16 + a_r) * LDSB + ks * 16 + a_c) * 2u;
                ldsm4(afh[i], sAh + off);
                ldsm4(afl[i], sAl + off);
            }
            uint32_t bfh[4][4], bfl[4][4];
#pragma unroll
            for (int jn = 0; jn < 4; jn++) {
                uint32_t off = (uint32_t)((wx * 64 + jn * 16 + b_r) * LDSB + ks * 16 + b_c) * 2u;
                ldsm4(bfh[jn], sBh + off);
                ldsm4(bfl[jn], sBl + off);
            }
#pragma unroll
            for (int i = 0; i < 2; i++)
#pragma unroll
                for (int jn = 0; jn < 4; jn++)
#pragma unroll
                    for (int hf = 0; hf < 2; hf++) {
                        int j8 = jn * 2 + hf;
                        mma16816(acc[i][j8], afh[i], &bfh[jn][hf * 2]);
                        mma16816(acc[i][j8], afh[i], &bfl[jn][hf * 2]);
                        mma16816(acc[i][j8], afl[i], &bfh[jn][hf * 2]);
                    }
        }
        __syncthreads();
        stage ^= 1;
    }

    // ---------------- epilogue --------------------------------------------
    const int er = lane >> 2;
    const int ec = (lane & 3) * 2;
#pragma unroll
    for (int i = 0; i < 2; i++) {
#pragma unroll
        for (int j8 = 0; j8 < 8; j8++) {
#pragma unroll
            for (int half = 0; half < 2; half++) {
                int m = m0 + wy * 32 + i * 16 + er + half * 8;
                int n = n0 + wx * 64 + j8 * 8 + ec;
                float v0 = acc[i][j8][half * 2 + 0];
                float v1 = acc[i][j8][half * 2 + 1];
                if (mode == 3) {
                    float2 o = make_float2(v0 + bias[n], v1 + bias[n + 1]);
                    *(float2*)(fout + (size_t)m * DD + n) = o;
                } else {
                    int b = m >> 11, s = m & (SS_ - 1);
                    int h = n >> 6, dh = n & 63;
                    float b0 = v0 + bias[n], b1 = v1 + bias[n + 1];
                    if (mode == 0) { b0 *= 0.125f; b1 *= 0.125f; }
                    __nv_bfloat16 h0, l0, h1, l1;
                    split2(b0, h0, l0);
                    split2(b1, h1, l1);
                    if (mode == 0) {
                        size_t di = (((size_t)(b * HH + h)) * SS_ + s) * HD + dh;
                        *(__nv_bfloat162*)(g_qh + di) = __halves2bfloat162(h0, h1);
                        *(__nv_bfloat162*)(g_ql + di) = __halves2bfloat162(l0, l1);
                    } else if (mode == 1) {
                        size_t di = (((size_t)(b * HH + h)) * SS_ + s) * HD + dh;
                        *(__nv_bfloat162*)(g_kh + di) = __halves2bfloat162(h0, h1);
                        *(__nv_bfloat162*)(g_kl + di) = __halves2bfloat162(l0, l1);
                    } else {   // mode == 2 : V^T [bh,dh,s]
                        size_t di = (((size_t)(b * HH + h)) * HD + dh) * SS_ + s;
                        g_vth[di] = h0; g_vtl[di] = l0;
                        g_vth[di + SS_] = h1; g_vtl[di + SS_] = l1;
                    }
                }
            }
        }
    }
}

// ============================================================================
// scores via mma, 128x128 CTA tile, K=64 (single load). grid (16,16,32)
// q pre-scaled by 1/8; writes P hi/lo.
// ============================================================================
__global__ __launch_bounds__(256) void scores_mma_kernel()
{
    extern __shared__ __align__(16) __nv_bfloat16 dynsm[];

    const int bh = blockIdx.z;
    const int m0 = blockIdx.x * 128;
    const int n0 = blockIdx.y * 128;
    const int tid = threadIdx.x;
    const int wid = tid >> 5;
    const int lane = tid & 31;

    const __nv_bfloat16* Qh = g_qh + (size_t)bh * SS_ * HD;
    const __nv_bfloat16* Ql = g_ql + (size_t)bh * SS_ * HD;
    const __nv_bfloat16* Kh = g_kh + (size_t)bh * SS_ * HD;
    const __nv_bfloat16* Kl = g_kl + (size_t)bh * SS_ * HD;

    const uint32_t sbase = smem_u32(dynsm);
    const uint32_t sAh = sbase;
    const uint32_t sAl = sbase + (uint32_t)(128 * LDSB) * 2u;
    const uint32_t sBh = sbase + (uint32_t)(2 * 128 * LDSB) * 2u;
    const uint32_t sBl = sbase + (uint32_t)(3 * 128 * LDSB) * 2u;

    // fill: 4 arrays x 128 rows x 8 chunks = 4096
    for (int idx = tid; idx < 4096; idx += 256) {
        int c = idx & 7;
        int r = (idx >> 3) & 127;
        int sel = idx >> 10;
        const __nv_bfloat16* src;
        uint32_t dst;
        if (sel == 0)      { src = Qh + (size_t)(m0 + r) * HD; dst = sAh; }
        else if (sel == 1) { src = Ql + (size_t)(m0 + r) * HD; dst = sAl; }
        else if (sel == 2) { src = Kh + (size_t)(n0 + r) * HD; dst = sBh; }
        else               { src = Kl + (size_t)(n0 + r) * HD; dst = sBl; }
        cp_async16(dst + (uint32_t)(r * LDSB + c * 8) * 2u, src + c * 8);
    }
    cp_async_commit();
    cp_async_wait0();
    __syncthreads();

    const int wy = wid >> 1;
    const int wx = wid & 1;
    const int a_r = lane & 15;
    const int a_c = (lane >> 4) << 3;
    const int b_r = ((lane >> 4) << 3) | (lane & 7);
    const int b_c = ((lane >> 3) & 1) << 3;

    float acc[2][8][4] = {};

#pragma unroll
    for (int ks = 0; ks < 4; ks++) {
        uint32_t afh[2][4], afl[2][4];
#pragma unroll
        for (int i = 0; i < 2; i++) {
            uint32_t off = (uint32_t)((wy * 32 + i * 16 + a_r) * LDSB + ks * 16 + a_c) * 2u;
            ldsm4(afh[i], sAh + off);
            ldsm4(afl[i], sAl + off);
        }
        uint32_t bfh[4][4], bfl[4][4];
#pragma unroll
        for (int jn = 0; jn < 4; jn++) {
            uint32_t off = (uint32_t)((wx * 64 + jn * 16 + b_r) * LDSB + ks * 16 + b_c) * 2u;
            ldsm4(bfh[jn], sBh + off);
            ldsm4(bfl[jn], sBl + off);
        }
#pragma unroll
        for (int i = 0; i < 2; i++)
#pragma unroll
            for (int jn = 0; jn < 4; jn++)
#pragma unroll
                for (int hf = 0; hf < 2; hf++) {
                    int j8 = jn * 2 + hf;
                    mma16816(acc[i][j8], afh[i], &bfh[jn][hf * 2]);
                    mma16816(acc[i][j8], afh[i], &bfl[jn][hf * 2]);
                    mma16816(acc[i][j8], afl[i], &bfh[jn][hf * 2]);
                }
    }

    __nv_bfloat16* __restrict__ Ph = g_ph + (size_t)bh * SSQ;
    __nv_bfloat16* __restrict__ Pl = g_pl + (size_t)bh * SSQ;
    const int er = lane >> 2;
    const int ec = (lane & 3) * 2;
#pragma unroll
    for (int i = 0; i < 2; i++) {
#pragma unroll
        for (int j8 = 0; j8 < 8; j8++) {
#pragma unroll
            for (int half = 0; half < 2; half++) {
                int m = m0 + wy * 32 + i * 16 + er + half * 8;
                int n = n0 + wx * 64 + j8 * 8 + ec;
                float v0 = acc[i][j8][half * 2 + 0];
                float v1 = acc[i][j8][half * 2 + 1];
                __nv_bfloat16 h0, l0, h1, l1;
                split2(v0, h0, l0);
                split2(v1, h1, l1);
                size_t di = (size_t)m * SS_ + n;
                *(__nv_bfloat162*)(Ph + di) = __halves2bfloat162(h0, h1);
                *(__nv_bfloat162*)(Pl + di) = __halves2bfloat162(l0, l1);
            }
        }
    }
}

// ============================================================================
// fused softmax + head-mean, vectorized (UNCHANGED, validated)
// ============================================================================
__global__ __launch_bounds__(256) void softmax_mean_kernel(float* __restrict__ attn_mean)
{
    const int bq = blockIdx.x;
    const int b = bq >> 11;
    const int q = bq & (SS_ - 1);
    const int tid = threadIdx.x;
    const int col0 = tid * 8;
    __shared__ float sm[8];

    float macc[8] = {};

    for (int h = 0; h < HH; h++) {
        const size_t row = ((size_t)(b * HH + h) * SS_ + q) * SS_;

        uint4 hv = *(const uint4*)(g_ph + row + col0);
        uint4 lv = *(const uint4*)(g_pl + row + col0);
        const __nv_bfloat162* hp = (const __nv_bfloat162*)&hv;
        const __nv_bfloat162* lp = (const __nv_bfloat162*)&lv;

        float v[8];
        float mx = -3.4e38f;
#pragma unroll
        for (int j = 0; j < 4; j++) {
            float2 a = __bfloat1622float2(hp[j]);
            float2 l2 = __bfloat1622float2(lp[j]);
            v[2 * j] = a.x + l2.x;
            v[2 * j + 1] = a.y + l2.y;
            mx = fmaxf(mx, fmaxf(v[2 * j], v[2 * j + 1]));
        }
#pragma unroll
        for (int o = 16; o; o >>= 1) mx = fmaxf(mx, __shfl_xor_sync(~0u, mx, o));
        if ((tid & 31) == 0) sm[tid >> 5] = mx;
        __syncthreads();
        mx = sm[0];
#pragma unroll
        for (int i = 1; i < 8; i++) mx = fmaxf(mx, sm[i]);
        __syncthreads();

        float sum = 0.f;
#pragma unroll
        for (int i = 0; i < 8; i++) { v[i] = __expf(v[i] - mx); sum += v[i]; }
#pragma unroll
        for (int o = 16; o; o >>= 1) sum += __shfl_xor_sync(~0u, sum, o);
        if ((tid & 31) == 0) sm[tid >> 5] = sum;
        __syncthreads();
        float total = 0.f;
#pragma unroll
        for (int i = 0; i < 8; i++) total += sm[i];
        __syncthreads();

        const float inv = 1.0f / total;
        uint4 ho, lo4;
        __nv_bfloat162* hop = (__nv_bfloat162*)&ho;
        __nv_bfloat162* lop = (__nv_bfloat162*)&lo4;
#pragma unroll
        for (int j = 0; j < 4; j++) {
            float p0 = v[2 * j] * inv;
            float p1 = v[2 * j + 1] * inv;
            macc[2 * j] += p0;
            macc[2 * j + 1] += p1;
            __nv_bfloat16 h0, l0, h1, l1;
            split2(p0, h0, l0);
            split2(p1, h1, l1);
            hop[j] = __halves2bfloat162(h0, h1);
            lop[j] = __halves2bfloat162(l0, l1);
        }
        *(uint4*)(g_ph + row + col0) = ho;
        *(uint4*)(g_pl + row + col0) = lo4;
    }

    const float inv16 = 1.0f / 16.0f;
    float* dst = attn_mean + (size_t)bq * SS_ + col0;
    float4 o0 = make_float4(macc[0] * inv16, macc[1] * inv16, macc[2] * inv16, macc[3] * inv16);
    float4 o1 = make_float4(macc[4] * inv16, macc[5] * inv16, macc[6] * inv16, macc[7] * inv16);
    *(float4*)(dst) = o0;
    *(float4*)(dst + 4) = o1;
}

// ============================================================================
// ctx = P @ V via mma, 2-stage cp.async (UNCHANGED, validated; DRAM-bound)
// ============================================================================
__global__ __launch_bounds__(256) void ctx_mma_kernel()
{
    extern __shared__ __align__(16) __nv_bfloat16 dynsm[];

    const int bh = blockIdx.y;
    const int m0 = blockIdx.x * 64;
    const int tid = threadIdx.x;
    const int wid = tid >> 5;
    const int lane = tid & 31;

    const __nv_bfloat16* Ph = g_ph + (size_t)bh * SSQ;
    const __nv_bfloat16* Pl = g_pl + (size_t)bh * SSQ;
    const __nv_bfloat16* Vh = g_vth + (size_t)bh * HD * SS_;
    const __nv_bfloat16* Vl = g_vtl + (size_t)bh * HD * SS_;

    const uint32_t sbase = smem_u32(dynsm);

    const int wy = wid >> 1;
    const int wx = wid & 1;
    const int a_r = lane & 15;
    const int a_c = (lane >> 4) << 3;
    const int b_r = ((lane >> 4) << 3) | (lane & 7);
    const int b_c = ((lane >> 3) & 1) << 3;

    float acc[4][4] = {};

    auto fill = [&](int it, int stage) {
        const int k0 = it * 64;
        const uint32_t stb = sbase + stage * C_STAGE_BYTES;
        for (int idx = tid; idx < 2048; idx += 256) {
            int c = idx & 7;
            int r = (idx >> 3) & 63;
            int sel = idx >> 9;
            const __nv_bfloat16* src;
            if (sel == 0)      src = Ph + (size_t)(m0 + r) * SS_ + k0;
            else if (sel == 1) src = Pl + (size_t)(m0 + r) * SS_ + k0;
            else if (sel == 2) src = Vh + (size_t)r * SS_ + k0;
            else               src = Vl + (size_t)r * SS_ + k0;
            uint32_t daddr = stb + (uint32_t)(sel * 64 * LDSB + r * LDSB + c * 8) * 2u;
            cp_async16(daddr, src + c * 8);
        }
    };

    fill(0, 0);
    cp_async_commit();
    int stage = 0;

    for (int it = 0; it < 32; ++it) {
        cp_async_wait0();
        __syncthreads();
        if (it + 1 < 32) { fill(it + 1, stage ^ 1); cp_async_commit(); }

        const uint32_t stb = sbase + stage * C_STAGE_BYTES;
        const uint32_t sAh = stb;
        const uint32_t sAl = stb + (uint32_t)(64 * LDSB) * 2u;
        const uint32_t sBh = stb + (uint32_t)(2 * 64 * LDSB) * 2u;
        const uint32_t sBl = stb + (uint32_t)(3 * 64 * LDSB) * 2u;

#pragma unroll
        for (int ks = 0; ks < 4; ks++) {
            uint32_t afh[4], afl[4];
            {
                uint32_t off = (uint32_t)((wy * 16 + a_r) * LDSB + ks * 16 + a_c) * 2u;
                ldsm4(afh, sAh + off);
                ldsm4(afl, sAl + off);
            }
            uint32_t bfh[2][4], bfl[2][4];
#pragma unroll
            for (int jn = 0; jn < 2; jn++) {
                uint32_t off = (uint32_t)((wx * 32 + jn * 16 + b_r) * LDSB + ks * 16 + b_c) * 2u;
                ldsm4(bfh[jn], sBh + off);
                ldsm4(bfl[jn], sBl + off);
            }
#pragma unroll
            for (int jn = 0; jn < 2; jn++)
#pragma unroll
                for (int hf = 0; hf < 2; hf++) {
                    int j8 = jn * 2 + hf;
                    mma16816(acc[j8], afh, &bfh[jn][hf * 2]);
                    mma16816(acc[j8], afh, &bfl[jn][hf * 2]);
                    mma16816(acc[j8], afl, &bfh[jn][hf * 2]);
                }
        }
        __syncthreads();
        stage ^= 1;
    }

    const int b = bh >> 4, h = bh & 15;
    const int er = lane >> 2;
    const int ec = (lane & 3) * 2;
#pragma unroll
    for (int j8 = 0; j8 < 4; j8++) {
#pragma unroll
        for (int half = 0; half < 2; half++) {
            int m = m0 + wy * 16 + er + half * 8;
            int n = wx * 32 + j8 * 8 + ec;        // dh
            float v0 = acc[j8][half * 2 + 0];
            float v1 = acc[j8][half * 2 + 1];
            __nv_bfloat16 h0, l0, h1, l1;
            split2(v0, h0, l0);
            split2(v1, h1, l1);
            size_t di = ((size_t)(b * SS_ + m)) * DD + h * HD + n;
            *(__nv_bfloat162*)(g_ch + di) = __halves2bfloat162(h0, h1);
            *(__nv_bfloat162*)(g_cl + di) = __halves2bfloat162(l0, l1);
        }
    }
}

// ============================================================================
extern "C" void kernel_launch(void* const* d_in, const int* in_sizes, int n_in,
                              void* d_out, int out_size)
{
    const float* x  = (const float*)d_in[0];
    const float* Wq = (const float*)d_in[1];
    const float* bq = (const float*)d_in[2];
    const float* Wk = (const float*)d_in[3];
    const float* bk = (const float*)d_in[4];
    const float* Wv = (const float*)d_in[5];
    const float* bv = (const float*)d_in[6];
    const float* Wo = (const float*)d_in[7];
    const float* bo = (const float*)d_in[8];

    float* out = (float*)d_out;                        // [B,S,D]
    float* attn_mean = out + (size_t)BB * SS_ * DD;    // [B,S,S]

    cudaFuncSetAttribute(gemm_mma_kernel,   cudaFuncAttributeMaxDynamicSharedMemorySize, G_PIPE_SMEM);
    cudaFuncSetAttribute(scores_mma_kernel, cudaFuncAttributeMaxDynamicSharedMemorySize, G_STAGE_BYTES);
    cudaFuncSetAttribute(ctx_mma_kernel,    cudaFuncAttributeMaxDynamicSharedMemorySize, C_PIPE_SMEM);

    // prep
    split_x_kernel<<<(M_TOT * DD + 255) / 256, 256>>>(x);
    dim3 tw(32, 8), gw(DD / 32, DD / 32);
    transpose_split_w_kernel<<<gw, tw>>>(Wq, 0);
    transpose_split_w_kernel<<<gw, tw>>>(Wk, 1);
    transpose_split_w_kernel<<<gw, tw>>>(Wv, 2);
    transpose_split_w_kernel<<<gw, tw>>>(Wo, 3);

    // projections: M=4096, N=1024, K=1024 with 128x128 tiles
    dim3 gp(M_TOT / 128, DD / 128);      // (32,8)
    gemm_mma_kernel<<<gp, 256, G_PIPE_SMEM>>>(0, bq, nullptr);
    gemm_mma_kernel<<<gp, 256, G_PIPE_SMEM>>>(1, bk, nullptr);
    gemm_mma_kernel<<<gp, 256, G_PIPE_SMEM>>>(2, bv, nullptr);

    // scores: 128x128 tiles
    dim3 gs(SS_ / 128, SS_ / 128, BH);   // (16,16,32)
    scores_mma_kernel<<<gs, 256, G_STAGE_BYTES>>>();

    // softmax + head mean
    softmax_mean_kernel<<<BB * SS_, 256>>>(attn_mean);

    // ctx
    dim3 gc(SS_ / 64, BH);               // (32,32)
    ctx_mma_kernel<<<gc, 256, C_PIPE_SMEM>>>();

    // out: 128x128 tiles
    gemm_mma_kernel<<<gp, 256, G_PIPE_SMEM>>>(3, bo, out);
}